// round 3
// baseline (speedup 1.0000x reference)
#include <cuda_runtime.h>
#include <math.h>

#define NN 100000
#define EE 1600000

// ---------------- scratch (device globals; no runtime allocation) ----------------
__device__ int   g_deg[NN];
__device__ int   g_rowp[NN + 1];
__device__ int   g_cur[NN];
__device__ int   g_esrc[EE];
__device__ float g_dinv[NN];
__device__ float g_t [NN * 128];   // fkan output (reused)
__device__ float g_h1[NN * 128];
__device__ float g_h2[NN * 128];
__device__ float g_t2[NN * 64];    // layer-2 fkan output, stride 64 (47 valid cols)

// ---------------- graph preprocessing ----------------
__global__ void k_zero_deg() {
    int i = blockIdx.x * blockDim.x + threadIdx.x;
    if (i < NN) g_deg[i] = 0;
}

__global__ void k_count(const int* __restrict__ ei) {
    int e = blockIdx.x * blockDim.x + threadIdx.x;
    if (e < EE) atomicAdd(&g_deg[ei[EE + e]], 1);
}

// single-block exclusive scan of g_deg -> g_rowp / g_cur
__global__ void k_scan() {
    __shared__ int wsum[32];
    __shared__ int scarry;
    int t = threadIdx.x, lane = t & 31, wid = t >> 5;
    if (t == 0) scarry = 0;
    __syncthreads();
    for (int base = 0; base < NN; base += 1024) {
        int i = base + t;
        int v = (i < NN) ? g_deg[i] : 0;
        int x = v;
        #pragma unroll
        for (int d = 1; d < 32; d <<= 1) {
            int y = __shfl_up_sync(0xffffffffu, x, d);
            if (lane >= d) x += y;
        }
        if (lane == 31) wsum[wid] = x;
        __syncthreads();
        if (wid == 0) {
            int ws = wsum[lane];
            #pragma unroll
            for (int d = 1; d < 32; d <<= 1) {
                int y = __shfl_up_sync(0xffffffffu, ws, d);
                if (lane >= d) ws += y;
            }
            wsum[lane] = ws;
        }
        __syncthreads();
        int carry = scarry;
        int excl = carry + (wid ? wsum[wid - 1] : 0) + (x - v);
        if (i < NN) { g_rowp[i] = excl; g_cur[i] = excl; }
        __syncthreads();
        if (t == 0) scarry = carry + wsum[31];
        __syncthreads();
    }
    if (t == 0) g_rowp[NN] = scarry;
}

__global__ void k_dinv() {
    int i = blockIdx.x * blockDim.x + threadIdx.x;
    if (i < NN) g_dinv[i] = rsqrtf((float)(g_deg[i] + 1));  // +1 self loop
}

__global__ void k_place(const int* __restrict__ ei) {
    int e = blockIdx.x * blockDim.x + threadIdx.x;
    if (e < EE) {
        int d = ei[EE + e];
        int pos = atomicAdd(&g_cur[d], 1);
        g_esrc[pos] = ei[e];
    }
}

// ---------------- fused FastKAN layer ----------------
// out[n,o] = sum_k silu(x[n,k])*Wb[o,k] + sum_{k,g} rbf(z[n,k],g)*Ws[o,k*4+g] + bs[o] + bb[o]
// z = layernorm(x)*gamma+beta,  rbf = exp(-((z-grid_g)*0.75)^2)
template<int DIN, int DOUT, int DOUT_PAD, int TM, int OUT_STRIDE>
__global__ __launch_bounds__(256)
void k_fkan(const float* __restrict__ in0, const float* __restrict__ in1,
            const float* __restrict__ in2,
            const float* __restrict__ lng, const float* __restrict__ lnb,
            const float* __restrict__ Ws,  const float* __restrict__ Wb,
            const float* __restrict__ bs,  const float* __restrict__ bb,
            float* __restrict__ out)
{
    constexpr int KC   = 64;
    constexpr int KTOT = DIN * 5;        // DIN base + DIN*4 spline
    constexpr int RM = 4, RN = 4;
    constexpr int TX = DOUT_PAD / RN;
    constexpr int TY = TM / RM;
    static_assert(TX * TY == 256, "thread tiling");
    constexpr int SXS = DIN + 1;
    constexpr int SWS = DOUT_PAD + 4;
    constexpr int GPR = 256 / TM;        // threads per row for LN reduce

    extern __shared__ float sm[];
    float* sx  = sm;                      // TM * SXS
    float* sW  = sx + TM * SXS;           // KC * SWS
    float* sA  = sW + KC * SWS;           // TM * KC
    float* smu = sA + TM * KC;            // TM
    float* srs = smu + TM;                // TM
    float* sg  = srs + TM;                // DIN
    float* sb  = sg + DIN;                // DIN

    const int t = threadIdx.x;
    const int base = blockIdx.x * TM;

    for (int i = t; i < DIN; i += 256) { sg[i] = lng[i]; sb[i] = lnb[i]; }

    // load input tile (handles 3-way concat for DIN==384)
    for (int e = t; e < TM * DIN; e += 256) {
        int r = e / DIN, c = e - r * DIN;
        int n = base + r;
        float v = 0.f;
        if (n < NN) {
            if (DIN == 384) {
                if (c < 128)      v = in0[n * 128 + c];
                else if (c < 256) v = in1[n * 128 + (c - 128)];
                else              v = in2[n * 128 + (c - 256)];
            } else {
                v = in0[n * DIN + c];
            }
        }
        sx[r * SXS + c] = v;
    }
    __syncthreads();

    // layernorm stats
    {
        int r = t / GPR, l = t % GPR;
        float s = 0.f, s2 = 0.f;
        for (int c = l; c < DIN; c += GPR) {
            float xv = sx[r * SXS + c];
            s += xv; s2 += xv * xv;
        }
        #pragma unroll
        for (int d = 1; d < GPR; d <<= 1) {
            s  += __shfl_xor_sync(0xffffffffu, s,  d);
            s2 += __shfl_xor_sync(0xffffffffu, s2, d);
        }
        if (l == 0) {
            float mu  = s * (1.f / DIN);
            float var = s2 * (1.f / DIN) - mu * mu;
            smu[r] = mu;
            srs[r] = rsqrtf(var + 1e-5f);
        }
    }
    __syncthreads();

    const int ty = t / TX, tx = t - ty * TX;
    float acc[RM][RN];
    #pragma unroll
    for (int r = 0; r < RM; r++)
        #pragma unroll
        for (int c = 0; c < RN; c++) acc[r][c] = 0.f;

    for (int kc = 0; kc < KTOT; kc += KC) {
        // ---- stage W chunk (transposed: sW[k][o]) ----
        const float* wsrc; int stride, koff;
        if (kc < DIN) { wsrc = Wb; stride = DIN;     koff = kc; }
        else          { wsrc = Ws; stride = DIN * 4; koff = kc - DIN; }
        for (int e = t; e < KC * DOUT_PAD; e += 256) {
            int o = e / KC, kk = e - o * KC;
            float w = (o < DOUT) ? wsrc[o * stride + koff + kk] : 0.f;
            sW[kk * SWS + o] = w;
        }
        // ---- stage A chunk (silu base / rbf spline on-the-fly) ----
        for (int e = t; e < TM * KC; e += 256) {
            int r = e / KC, kk = e - r * KC;
            int kg = kc + kk;
            float v;
            if (kg < DIN) {
                float xv = sx[r * SXS + kg];
                v = xv / (1.f + __expf(-xv));
            } else {
                int j = kg - DIN;
                int k2 = j >> 2, g = j & 3;
                float z = (sx[r * SXS + k2] - smu[r]) * srs[r] * sg[k2] + sb[k2];
                float gr = -2.f + (float)g * (4.f / 3.f);
                float u = (z - gr) * 0.75f;   // 1/denom = 3/4
                v = __expf(-u * u);
            }
            sA[r * KC + kk] = v;
        }
        __syncthreads();

        // ---- register-blocked FMA ----
        #pragma unroll 4
        for (int k4 = 0; k4 < KC / 4; k4++) {
            float4 av[RM];
            #pragma unroll
            for (int r = 0; r < RM; r++)
                av[r] = *(const float4*)&sA[(ty * RM + r) * KC + k4 * 4];
            #pragma unroll
            for (int kk = 0; kk < 4; kk++) {
                float4 wv = *(const float4*)&sW[(k4 * 4 + kk) * SWS + tx * RN];
                #pragma unroll
                for (int r = 0; r < RM; r++) {
                    float a = (kk == 0) ? av[r].x : (kk == 1) ? av[r].y
                            : (kk == 2) ? av[r].z : av[r].w;
                    acc[r][0] += a * wv.x;
                    acc[r][1] += a * wv.y;
                    acc[r][2] += a * wv.z;
                    acc[r][3] += a * wv.w;
                }
            }
        }
        __syncthreads();
    }

    #pragma unroll
    for (int r = 0; r < RM; r++) {
        int n = base + ty * RM + r;
        if (n >= NN) continue;
        #pragma unroll
        for (int c = 0; c < RN; c++) {
            int o = tx * RN + c;
            if (o < DOUT)
                out[(long)n * OUT_STRIDE + o] = acc[r][c] + bs[o] + bb[o];
        }
    }
}

// ---------------- aggregation (warp per node, CSR, no atomics) ----------------
__global__ void k_agg128(const float* __restrict__ tin, float* __restrict__ outp,
                         const float* __restrict__ bg) {
    int gw = (blockIdx.x * blockDim.x + threadIdx.x) >> 5;
    int lane = threadIdx.x & 31;
    if (gw >= NN) return;
    int n = gw;
    int beg = g_rowp[n], end = g_rowp[n + 1];
    const float4* t4 = (const float4*)tin;
    float4 a0 = {0, 0, 0, 0}, a1 = {0, 0, 0, 0};
    int j = beg;
    for (; j + 1 < end; j += 2) {
        int s0 = g_esrc[j], s1 = g_esrc[j + 1];
        float w0 = g_dinv[s0], w1 = g_dinv[s1];
        float4 v0 = t4[s0 * 32 + lane];
        float4 v1 = t4[s1 * 32 + lane];
        a0.x += w0 * v0.x; a0.y += w0 * v0.y; a0.z += w0 * v0.z; a0.w += w0 * v0.w;
        a1.x += w1 * v1.x; a1.y += w1 * v1.y; a1.z += w1 * v1.z; a1.w += w1 * v1.w;
    }
    if (j < end) {
        int s0 = g_esrc[j];
        float w0 = g_dinv[s0];
        float4 v0 = t4[s0 * 32 + lane];
        a0.x += w0 * v0.x; a0.y += w0 * v0.y; a0.z += w0 * v0.z; a0.w += w0 * v0.w;
    }
    float dn = g_dinv[n];
    float4 sv = t4[n * 32 + lane];
    float4 bgv = ((const float4*)bg)[lane];
    float4 o;
    o.x = dn * (a0.x + a1.x + dn * sv.x) + bgv.x;
    o.y = dn * (a0.y + a1.y + dn * sv.y) + bgv.y;
    o.z = dn * (a0.z + a1.z + dn * sv.z) + bgv.z;
    o.w = dn * (a0.w + a1.w + dn * sv.w) + bgv.w;
    ((float4*)outp)[n * 32 + lane] = o;
}

__global__ void k_agg47(const float* __restrict__ tin, float* __restrict__ outp,
                        const float* __restrict__ bg) {
    int gw = (blockIdx.x * blockDim.x + threadIdx.x) >> 5;
    int lane = threadIdx.x & 31;
    if (gw >= NN) return;
    int n = gw;
    int beg = g_rowp[n], end = g_rowp[n + 1];
    float a0 = 0.f, a1 = 0.f;
    for (int j = beg; j < end; j++) {
        int s = g_esrc[j];
        float w = g_dinv[s];
        const float* ts = tin + s * 64;
        a0 += w * ts[lane];
        if (lane < 15) a1 += w * ts[32 + lane];
    }
    float dn = g_dinv[n];
    const float* tn = tin + n * 64;
    outp[n * 47 + lane] = dn * (a0 + dn * tn[lane]) + bg[lane];
    if (lane < 15)
        outp[n * 47 + 32 + lane] = dn * (a1 + dn * tn[32 + lane]) + bg[32 + lane];
}

// ---------------- driver ----------------
extern "C" void kernel_launch(void* const* d_in, const int* in_sizes, int n_in,
                              void* d_out, int out_size) {
    const float* x    = (const float*)d_in[0];
    const int*   ei   = (const int*)d_in[1];
    const float* lng0 = (const float*)d_in[2];
    const float* lnb0 = (const float*)d_in[3];
    const float* Ws0  = (const float*)d_in[4];
    const float* bs0  = (const float*)d_in[5];
    const float* Wb0  = (const float*)d_in[6];
    const float* bb0  = (const float*)d_in[7];
    const float* bg0  = (const float*)d_in[8];
    const float* lng1 = (const float*)d_in[9];
    const float* lnb1 = (const float*)d_in[10];
    const float* Ws1  = (const float*)d_in[11];
    const float* bs1  = (const float*)d_in[12];
    const float* Wb1  = (const float*)d_in[13];
    const float* bb1  = (const float*)d_in[14];
    const float* bg1  = (const float*)d_in[15];
    const float* lng2 = (const float*)d_in[16];
    const float* lnb2 = (const float*)d_in[17];
    const float* Ws2  = (const float*)d_in[18];
    const float* bs2  = (const float*)d_in[19];
    const float* Wb2  = (const float*)d_in[20];
    const float* bb2  = (const float*)d_in[21];
    const float* bg2  = (const float*)d_in[22];
    float* outp = (float*)d_out;

    void *pt, *ph1, *ph2, *pt2;
    cudaGetSymbolAddress(&pt,  g_t);
    cudaGetSymbolAddress(&ph1, g_h1);
    cudaGetSymbolAddress(&ph2, g_h2);
    cudaGetSymbolAddress(&pt2, g_t2);

    // dynamic smem sizes
    const int SM_L01 = (32 * 129 + 64 * 132 + 32 * 64 + 32 + 32 + 128 + 128) * 4;   // 59776 B
    const int SM_L2  = (64 * 385 + 64 * 68 + 64 * 64 + 64 + 64 + 384 + 384) * 4;    // 135936 B
    cudaFuncSetAttribute(k_fkan<128, 128, 128, 32, 128>,
                         cudaFuncAttributeMaxDynamicSharedMemorySize, SM_L01);
    cudaFuncSetAttribute(k_fkan<384, 47, 64, 64, 64>,
                         cudaFuncAttributeMaxDynamicSharedMemorySize, SM_L2);

    // graph preprocessing -> CSR + dinv
    k_zero_deg<<<(NN + 255) / 256, 256>>>();
    k_count<<<(EE + 255) / 256, 256>>>(ei);
    k_scan<<<1, 1024>>>();
    k_dinv<<<(NN + 255) / 256, 256>>>();
    k_place<<<(EE + 255) / 256, 256>>>(ei);

    const int FKAN_GRID_01 = (NN + 31) / 32;   // 3125
    const int FKAN_GRID_2  = (NN + 63) / 64;   // 1563
    const int AGG_GRID     = (NN * 32 + 255) / 256;  // warp per node

    // layer 0: x -> h1
    k_fkan<128, 128, 128, 32, 128><<<FKAN_GRID_01, 256, SM_L01>>>(
        x, nullptr, nullptr, lng0, lnb0, Ws0, Wb0, bs0, bb0, (float*)pt);
    k_agg128<<<AGG_GRID, 256>>>((const float*)pt, (float*)ph1, bg0);

    // layer 1: h1 -> h2
    k_fkan<128, 128, 128, 32, 128><<<FKAN_GRID_01, 256, SM_L01>>>(
        (const float*)ph1, nullptr, nullptr, lng1, lnb1, Ws1, Wb1, bs1, bb1, (float*)pt);
    k_agg128<<<AGG_GRID, 256>>>((const float*)pt, (float*)ph2, bg1);

    // layer 2: [x, h1, h2] -> out
    k_fkan<384, 47, 64, 64, 64><<<FKAN_GRID_2, 256, SM_L2>>>(
        x, (const float*)ph1, (const float*)ph2, lng2, lnb2, Ws2, Wb2, bs2, bb2,
        (float*)pt2);
    k_agg47<<<AGG_GRID, 256>>>((const float*)pt2, outp, bg2);
}

// round 5
// speedup vs baseline: 2.4743x; 2.4743x over previous
#include <cuda_runtime.h>
#include <cuda_bf16.h>
#include <mma.h>
#include <cstdint>
#include <math.h>

using namespace nvcuda;

#define NN 100000
#define EE 1600000

// ---------------- scratch (device globals; no runtime allocation) ----------------
__device__ int   g_deg[NN];
__device__ int   g_rowp[NN + 1];
__device__ int   g_cur[NN];
__device__ int   g_esrc[EE];
__device__ float g_dinv[NN];
__device__ float g_mu[NN];
__device__ float g_rs[NN];
__device__ float g_t [NN * 128];
__device__ float g_h1[NN * 128];
__device__ float g_h2[NN * 128];
__device__ float g_t2[NN * 64];
// packed bf16-split weights: per chunk [hi 32*NPADP][lo 32*NPADP]
__device__ __align__(16) __nv_bfloat16 g_wb0[20 * 2 * 32 * 136];
__device__ __align__(16) __nv_bfloat16 g_wb1[20 * 2 * 32 * 136];
__device__ __align__(16) __nv_bfloat16 g_wb2[60 * 2 * 32 * 56];

// ---------------- graph preprocessing ----------------
__global__ void k_zero_deg() {
    int i = blockIdx.x * blockDim.x + threadIdx.x;
    if (i < NN) g_deg[i] = 0;
}
__global__ void k_count(const int* __restrict__ ei) {
    int e = blockIdx.x * blockDim.x + threadIdx.x;
    if (e < EE) atomicAdd(&g_deg[ei[EE + e]], 1);
}
__global__ void k_scan() {
    __shared__ int wsum[32];
    __shared__ int scarry;
    int t = threadIdx.x, lane = t & 31, wid = t >> 5;
    if (t == 0) scarry = 0;
    __syncthreads();
    for (int base = 0; base < NN; base += 1024) {
        int i = base + t;
        int v = (i < NN) ? g_deg[i] : 0;
        int x = v;
        #pragma unroll
        for (int d = 1; d < 32; d <<= 1) {
            int y = __shfl_up_sync(0xffffffffu, x, d);
            if (lane >= d) x += y;
        }
        if (lane == 31) wsum[wid] = x;
        __syncthreads();
        if (wid == 0) {
            int ws = wsum[lane];
            #pragma unroll
            for (int d = 1; d < 32; d <<= 1) {
                int y = __shfl_up_sync(0xffffffffu, ws, d);
                if (lane >= d) ws += y;
            }
            wsum[lane] = ws;
        }
        __syncthreads();
        int carry = scarry;
        int excl = carry + (wid ? wsum[wid - 1] : 0) + (x - v);
        if (i < NN) { g_rowp[i] = excl; g_cur[i] = excl; }
        __syncthreads();
        if (t == 0) scarry = carry + wsum[31];
        __syncthreads();
    }
    if (t == 0) g_rowp[NN] = scarry;
}
__global__ void k_dinv() {
    int i = blockIdx.x * blockDim.x + threadIdx.x;
    if (i < NN) g_dinv[i] = rsqrtf((float)(g_deg[i] + 1));
}
__global__ void k_place(const int* __restrict__ ei) {
    int e = blockIdx.x * blockDim.x + threadIdx.x;
    if (e < EE) {
        int d = ei[EE + e];
        int pos = atomicAdd(&g_cur[d], 1);
        g_esrc[pos] = ei[e];
    }
}

// ---------------- weight precompute: bf16 hi/lo, chunk-packed ----------------
// layout: [chunk][hi=0|lo=1][k 0..31][n 0..NPADP)
template<int DIN, int DOUT, int NPAD, int NPADP>
__global__ void k_prepw(const float* __restrict__ Wb, const float* __restrict__ Ws,
                        __nv_bfloat16* __restrict__ dst) {
    constexpr int NCH = DIN * 5 / 32;
    int idx = blockIdx.x * blockDim.x + threadIdx.x;
    if (idx >= NCH * 2 * 32 * NPADP) return;
    int n = idx % NPADP;
    int k = (idx / NPADP) & 31;
    int h = (idx / (NPADP * 32)) & 1;
    int c = idx / (NPADP * 32 * 2);
    int kg = c * 32 + k;
    float w = 0.f;
    if (n < DOUT) {
        if (kg < DIN) w = Wb[(size_t)n * DIN + kg];
        else          w = Ws[(size_t)n * (DIN * 4) + (kg - DIN)];
    }
    __nv_bfloat16 hi = __float2bfloat16(w);
    __nv_bfloat16 lo = __float2bfloat16(w - __bfloat162float(hi));
    dst[idx] = h ? lo : hi;
}

// ---------------- layernorm stats (warp per node) ----------------
__global__ void k_stats(const float* __restrict__ a, const float* __restrict__ b,
                        const float* __restrict__ c, int nseg) {
    int gw = (blockIdx.x * blockDim.x + threadIdx.x) >> 5;
    int lane = threadIdx.x & 31;
    if (gw >= NN) return;
    const float* ptrs[3] = {a, b, c};
    float s = 0.f, s2 = 0.f;
    for (int seg = 0; seg < nseg; seg++) {
        float4 v = ((const float4*)(ptrs[seg] + (size_t)gw * 128))[lane];
        s  += v.x + v.y + v.z + v.w;
        s2 += v.x * v.x + v.y * v.y + v.z * v.z + v.w * v.w;
    }
    #pragma unroll
    for (int d = 16; d; d >>= 1) {
        s  += __shfl_xor_sync(0xffffffffu, s,  d);
        s2 += __shfl_xor_sync(0xffffffffu, s2, d);
    }
    if (lane == 0) {
        float din = (float)(nseg * 128);
        float m = s / din;
        g_mu[gw] = m;
        g_rs[gw] = rsqrtf(s2 / din - m * m + 1e-5f);
    }
}

// ---------------- fused FastKAN layer via wmma bf16 (3-term compensation) ----------------
template<int DIN>
__device__ __forceinline__ float4 ldx4(const float* __restrict__ a,
                                       const float* __restrict__ b,
                                       const float* __restrict__ c,
                                       int n, int col) {
    if (DIN == 128) return *(const float4*)(a + (size_t)n * 128 + col);
    const float* p = (col < 128) ? a : (col < 256) ? b : c;
    return *(const float4*)(p + (size_t)n * 128 + (col & 127));
}

__device__ __forceinline__ void splitstore(__nv_bfloat16* hiP, __nv_bfloat16* loP,
                                           float4 v) {
    __nv_bfloat162 h0 = __floats2bfloat162_rn(v.x, v.y);
    __nv_bfloat162 h1 = __floats2bfloat162_rn(v.z, v.w);
    float2 f0 = __bfloat1622float2(h0);
    float2 f1 = __bfloat1622float2(h1);
    __nv_bfloat162 l0 = __floats2bfloat162_rn(v.x - f0.x, v.y - f0.y);
    __nv_bfloat162 l1 = __floats2bfloat162_rn(v.z - f1.x, v.w - f1.y);
    ((__nv_bfloat162*)hiP)[0] = h0;
    ((__nv_bfloat162*)hiP)[1] = h1;
    ((__nv_bfloat162*)loP)[0] = l0;
    ((__nv_bfloat162*)loP)[1] = l1;
}

// A smem: 128 x 40 (padded) bf16, hi + lo.  B smem: 32 x NPADP bf16, hi + lo.
template<int DIN, int DOUT, int NPAD, int NPADP, int OUTP, int OUT_STRIDE>
__global__ void __launch_bounds__(256)
k_fkan_wmma(const float* __restrict__ in0, const float* __restrict__ in1,
            const float* __restrict__ in2,
            const float* __restrict__ lng, const float* __restrict__ lnb,
            const __nv_bfloat16* __restrict__ wp,
            float* __restrict__ out)
{
    constexpr int NCH = DIN * 5 / 32;
    constexpr int NT  = NPAD / 16;
    constexpr int ALD = 40;

    extern __shared__ char smc[];
    __nv_bfloat16* aHi = (__nv_bfloat16*)smc;             // 128*40
    __nv_bfloat16* aLo = aHi + 128 * ALD;                 // 128*40
    __nv_bfloat16* bHi = aLo + 128 * ALD;                 // 32*NPADP
    float* sOut = (float*)smc;                            // epilogue reuse

    const int t = threadIdx.x;
    const int w = t >> 5;
    const int base = blockIdx.x * 128;

    const int r = t >> 1, half = t & 1;
    const int n = base + r;
    const bool valid = (n < NN);
    const float mu = valid ? g_mu[n] : 0.f;
    const float rs = valid ? g_rs[n] : 0.f;

    wmma::fragment<wmma::accumulator, 16, 16, 16, float> acc[NT];
    #pragma unroll
    for (int i = 0; i < NT; i++) wmma::fill_fragment(acc[i], 0.f);

    for (int c = 0; c < NCH; c++) {
        const int kc = c * 32;

        // ---- A staging: silu base / rbf spline, bf16 hi/lo ----
        if (kc < DIN) {
            #pragma unroll
            for (int q = 0; q < 4; q++) {
                const int c0 = half * 16 + q * 4;
                float4 xv = make_float4(0.f, 0.f, 0.f, 0.f);
                if (valid) xv = ldx4<DIN>(in0, in1, in2, n, kc + c0);
                float4 v;
                v.x = __fdividef(xv.x, 1.f + __expf(-xv.x));
                v.y = __fdividef(xv.y, 1.f + __expf(-xv.y));
                v.z = __fdividef(xv.z, 1.f + __expf(-xv.z));
                v.w = __fdividef(xv.w, 1.f + __expf(-xv.w));
                splitstore(aHi + r * ALD + c0, aLo + r * ALD + c0, v);
            }
        } else {
            const int xc = ((kc - DIN) >> 2) + half * 4;
            float4 xv = make_float4(0.f, 0.f, 0.f, 0.f);
            if (valid) xv = ldx4<DIN>(in0, in1, in2, n, xc);
            const float4 gv = *(const float4*)(lng + xc);
            const float4 bv = *(const float4*)(lnb + xc);
            float zz[4];
            zz[0] = (xv.x - mu) * rs * gv.x + bv.x;
            zz[1] = (xv.y - mu) * rs * gv.y + bv.y;
            zz[2] = (xv.z - mu) * rs * gv.z + bv.z;
            zz[3] = (xv.w - mu) * rs * gv.w + bv.w;
            #pragma unroll
            for (int i = 0; i < 4; i++) {
                float4 v;
                float u;
                u = (zz[i] + 2.f) * 0.75f;               v.x = __expf(-u * u);
                u = (zz[i] + 2.f - 4.f / 3.f) * 0.75f;   v.y = __expf(-u * u);
                u = (zz[i] + 2.f - 8.f / 3.f) * 0.75f;   v.z = __expf(-u * u);
                u = (zz[i] - 2.f) * 0.75f;               v.w = __expf(-u * u);
                const int c0 = half * 16 + i * 4;
                splitstore(aHi + r * ALD + c0, aLo + r * ALD + c0, v);
            }
        }

        // ---- B staging: straight copy of pre-split weights (hi then lo) ----
        {
            constexpr int NV4 = 2 * 32 * NPADP * 2 / 16;
            const float4* src = (const float4*)(wp + (size_t)c * (2 * 32 * NPADP));
            float4* dst = (float4*)bHi;
            #pragma unroll
            for (int i = t; i < NV4; i += 256) dst[i] = src[i];
        }
        __syncthreads();

        // ---- wmma compute: Ah*Bh + Ah*Bl + Al*Bh ----
        #pragma unroll
        for (int kk = 0; kk < 2; kk++) {
            wmma::fragment<wmma::matrix_a, 16, 16, 16, __nv_bfloat16, wmma::row_major> ah, al;
            wmma::load_matrix_sync(ah, aHi + w * 16 * ALD + kk * 16, ALD);
            wmma::load_matrix_sync(al, aLo + w * 16 * ALD + kk * 16, ALD);
            #pragma unroll
            for (int nt = 0; nt < NT; nt++) {
                wmma::fragment<wmma::matrix_b, 16, 16, 16, __nv_bfloat16, wmma::row_major> bh, bl;
                wmma::load_matrix_sync(bh, bHi + kk * 16 * NPADP + nt * 16, NPADP);
                wmma::load_matrix_sync(bl, bHi + 32 * NPADP + kk * 16 * NPADP + nt * 16, NPADP);
                wmma::mma_sync(acc[nt], ah, bh, acc[nt]);
                wmma::mma_sync(acc[nt], ah, bl, acc[nt]);
                wmma::mma_sync(acc[nt], al, bh, acc[nt]);
            }
        }
        __syncthreads();
    }

    // ---- epilogue: accs -> smem -> guarded global store (no bias; folded into agg) ----
    #pragma unroll
    for (int nt = 0; nt < NT; nt++)
        wmma::store_matrix_sync(sOut + w * 16 * OUTP + nt * 16, acc[nt], OUTP,
                                wmma::mem_row_major);
    __syncthreads();

    if (NPAD == 128) {
        for (int e = t; e < 128 * 32; e += 256) {
            int rr = e >> 5, c4 = e & 31;
            int n2 = base + rr;
            if (n2 < NN)
                ((float4*)(out + (size_t)n2 * OUT_STRIDE))[c4] =
                    *(float4*)&sOut[rr * OUTP + c4 * 4];
        }
    } else {
        for (int e = t; e < 128 * NPAD; e += 256) {
            int rr = e / NPAD, o = e % NPAD;
            int n2 = base + rr;
            if (o < DOUT && n2 < NN)
                out[(size_t)n2 * OUT_STRIDE + o] = sOut[rr * OUTP + o];
        }
    }
}

// ---------------- aggregation (warp per node, CSR, bias folded) ----------------
__global__ void k_agg128(const float* __restrict__ tin, float* __restrict__ outp,
                         const float* __restrict__ bs, const float* __restrict__ bb,
                         const float* __restrict__ bg) {
    int gw = (blockIdx.x * blockDim.x + threadIdx.x) >> 5;
    int lane = threadIdx.x & 31;
    if (gw >= NN) return;
    int beg = g_rowp[gw], end = g_rowp[gw + 1];
    const float4* t4 = (const float4*)tin;
    float4 a = make_float4(0.f, 0.f, 0.f, 0.f);
    float sw = 0.f;
    int j = beg;
    for (; j + 1 < end; j += 2) {
        int s0 = g_esrc[j], s1 = g_esrc[j + 1];
        float w0 = g_dinv[s0], w1 = g_dinv[s1];
        sw += w0 + w1;
        float4 v0 = t4[(size_t)s0 * 32 + lane];
        float4 v1 = t4[(size_t)s1 * 32 + lane];
        a.x += w0 * v0.x + w1 * v1.x;
        a.y += w0 * v0.y + w1 * v1.y;
        a.z += w0 * v0.z + w1 * v1.z;
        a.w += w0 * v0.w + w1 * v1.w;
    }
    if (j < end) {
        int s0 = g_esrc[j];
        float w0 = g_dinv[s0];
        sw += w0;
        float4 v0 = t4[(size_t)s0 * 32 + lane];
        a.x += w0 * v0.x; a.y += w0 * v0.y; a.z += w0 * v0.z; a.w += w0 * v0.w;
    }
    float dn = g_dinv[gw];
    float wb = dn * (sw + dn);   // bias weight: sum of norms incl self
    float4 sv = t4[(size_t)gw * 32 + lane];
    float4 bgv = ((const float4*)bg)[lane];
    float4 bsv = ((const float4*)bs)[lane];
    float4 bbv = ((const float4*)bb)[lane];
    float4 o;
    o.x = dn * (a.x + dn * sv.x) + (bsv.x + bbv.x) * wb + bgv.x;
    o.y = dn * (a.y + dn * sv.y) + (bsv.y + bbv.y) * wb + bgv.y;
    o.z = dn * (a.z + dn * sv.z) + (bsv.z + bbv.z) * wb + bgv.z;
    o.w = dn * (a.w + dn * sv.w) + (bsv.w + bbv.w) * wb + bgv.w;
    ((float4*)outp)[(size_t)gw * 32 + lane] = o;
}

__global__ void k_agg47(const float* __restrict__ tin, float* __restrict__ outp,
                        const float* __restrict__ bs, const float* __restrict__ bb,
                        const float* __restrict__ bg) {
    int gw = (blockIdx.x * blockDim.x + threadIdx.x) >> 5;
    int lane = threadIdx.x & 31;
    if (gw >= NN) return;
    int beg = g_rowp[gw], end = g_rowp[gw + 1];
    float a0 = 0.f, a1 = 0.f, sw = 0.f;
    for (int j = beg; j < end; j++) {
        int s = g_esrc[j];
        float w = g_dinv[s];
        sw += w;
        const float* ts = tin + (size_t)s * 64;
        a0 += w * ts[lane];
        if (lane < 15) a1 += w * ts[32 + lane];
    }
    float dn = g_dinv[gw];
    float wb = dn * (sw + dn);
    const float* tn = tin + (size_t)gw * 64;
    outp[(size_t)gw * 47 + lane] =
        dn * (a0 + dn * tn[lane]) + (bs[lane] + bb[lane]) * wb + bg[lane];
    if (lane < 15)
        outp[(size_t)gw * 47 + 32 + lane] =
            dn * (a1 + dn * tn[32 + lane]) + (bs[32 + lane] + bb[32 + lane]) * wb + bg[32 + lane];
}

// ---------------- driver ----------------
extern "C" void kernel_launch(void* const* d_in, const int* in_sizes, int n_in,
                              void* d_out, int out_size) {
    const float* x    = (const float*)d_in[0];
    const int*   ei   = (const int*)d_in[1];
    const float* lng0 = (const float*)d_in[2];
    const float* lnb0 = (const float*)d_in[3];
    const float* Ws0  = (const float*)d_in[4];
    const float* bs0  = (const float*)d_in[5];
    const float* Wb0  = (const float*)d_in[6];
    const float* bb0  = (const float*)d_in[7];
    const float* bg0  = (const float*)d_in[8];
    const float* lng1 = (const float*)d_in[9];
    const float* lnb1 = (const float*)d_in[10];
    const float* Ws1  = (const float*)d_in[11];
    const float* bs1  = (const float*)d_in[12];
    const float* Wb1  = (const float*)d_in[13];
    const float* bb1  = (const float*)d_in[14];
    const float* bg1  = (const float*)d_in[15];
    const float* lng2 = (const float*)d_in[16];
    const float* lnb2 = (const float*)d_in[17];
    const float* Ws2  = (const float*)d_in[18];
    const float* bs2  = (const float*)d_in[19];
    const float* Wb2  = (const float*)d_in[20];
    const float* bb2  = (const float*)d_in[21];
    const float* bg2  = (const float*)d_in[22];
    float* outp = (float*)d_out;

    void *pt, *ph1, *ph2, *pt2, *pw0, *pw1, *pw2;
    cudaGetSymbolAddress(&pt,  g_t);
    cudaGetSymbolAddress(&ph1, g_h1);
    cudaGetSymbolAddress(&ph2, g_h2);
    cudaGetSymbolAddress(&pt2, g_t2);
    cudaGetSymbolAddress(&pw0, g_wb0);
    cudaGetSymbolAddress(&pw1, g_wb1);
    cudaGetSymbolAddress(&pw2, g_wb2);

    // smem: L01 epilogue dominates (128*132*4); L2 staging dominates
    const int SM_L01 = 128 * 132 * 4;                       // 67584
    const int SM_L2  = 2 * 128 * 40 * 2 + 2 * 32 * 56 * 2;  // 27648
    cudaFuncSetAttribute((const void*)k_fkan_wmma<128, 128, 128, 136, 132, 128>,
                         cudaFuncAttributeMaxDynamicSharedMemorySize, SM_L01);
    cudaFuncSetAttribute((const void*)k_fkan_wmma<384, 47, 48, 56, 52, 64>,
                         cudaFuncAttributeMaxDynamicSharedMemorySize, SM_L2);

    // graph preprocessing -> CSR + dinv
    k_zero_deg<<<(NN + 255) / 256, 256>>>();
    k_count<<<(EE + 255) / 256, 256>>>(ei);
    k_scan<<<1, 1024>>>();
    k_dinv<<<(NN + 255) / 256, 256>>>();
    k_place<<<(EE + 255) / 256, 256>>>(ei);

    // weight precompute (bf16 split, chunk-packed)
    k_prepw<128, 128, 128, 136><<<(20 * 2 * 32 * 136 + 255) / 256, 256>>>(
        Wb0, Ws0, (__nv_bfloat16*)pw0);
    k_prepw<128, 128, 128, 136><<<(20 * 2 * 32 * 136 + 255) / 256, 256>>>(
        Wb1, Ws1, (__nv_bfloat16*)pw1);
    k_prepw<384, 47, 48, 56><<<(60 * 2 * 32 * 56 + 255) / 256, 256>>>(
        Wb2, Ws2, (__nv_bfloat16*)pw2);

    const int FG = (NN + 127) / 128;          // 782
    const int SG = (NN * 32 + 255) / 256;     // warp per node

    // layer 0
    k_stats<<<SG, 256>>>(x, x, x, 1);
    k_fkan_wmma<128, 128, 128, 136, 132, 128><<<FG, 256, SM_L01>>>(
        x, nullptr, nullptr, lng0, lnb0, (const __nv_bfloat16*)pw0, (float*)pt);
    k_agg128<<<SG, 256>>>((const float*)pt, (float*)ph1, bs0, bb0, bg0);

    // layer 1
    k_stats<<<SG, 256>>>((const float*)ph1, (const float*)ph1, (const float*)ph1, 1);
    k_fkan_wmma<128, 128, 128, 136, 132, 128><<<FG, 256, SM_L01>>>(
        (const float*)ph1, nullptr, nullptr, lng1, lnb1, (const __nv_bfloat16*)pw1,
        (float*)pt);
    k_agg128<<<SG, 256>>>((const float*)pt, (float*)ph2, bs1, bb1, bg1);

    // layer 2
    k_stats<<<SG, 256>>>(x, (const float*)ph1, (const float*)ph2, 3);
    k_fkan_wmma<384, 47, 48, 56, 52, 64><<<FG, 256, SM_L2>>>(
        x, (const float*)ph1, (const float*)ph2, lng2, lnb2,
        (const __nv_bfloat16*)pw2, (float*)pt2);
    k_agg47<<<SG, 256>>>((const float*)pt2, outp, bs2, bb2, bg2);
}

// round 6
// speedup vs baseline: 2.7279x; 1.1025x over previous
#include <cuda_runtime.h>
#include <cuda_bf16.h>
#include <mma.h>
#include <cstdint>
#include <math.h>

using namespace nvcuda;

#define NN 100000
#define EE 1600000

// ---------------- scratch (device globals; no runtime allocation) ----------------
__device__ int   g_deg[NN];
__device__ int   g_rowp[NN + 1];
__device__ int   g_cur[NN];
__device__ int   g_esrc[EE];
__device__ float g_dinv[NN];
__device__ float g_mu[NN];
__device__ float g_rs[NN];
__device__ float g_sA[NN];    // running partial sum   (x, then x+h1)
__device__ float g_sA2[NN];   // running partial sumsq
__device__ float g_t [NN * 128];
__device__ float g_h1[NN * 128];
__device__ float g_h2[NN * 128];
__device__ float g_t2[NN * 64];
// packed bf16-split weights: per chunk [hi 32*NPADP][lo 32*NPADP]
__device__ __align__(16) __nv_bfloat16 g_wb0[20 * 2 * 32 * 136];
__device__ __align__(16) __nv_bfloat16 g_wb1[20 * 2 * 32 * 136];
__device__ __align__(16) __nv_bfloat16 g_wb2[60 * 2 * 32 * 56];

// ---------------- graph preprocessing ----------------
__global__ void k_zero_deg() {
    int i = blockIdx.x * blockDim.x + threadIdx.x;
    if (i < NN) g_deg[i] = 0;
}
__global__ void k_count(const int* __restrict__ ei) {
    int e = blockIdx.x * blockDim.x + threadIdx.x;
    if (e < EE) atomicAdd(&g_deg[ei[EE + e]], 1);
}
__global__ void k_scan() {
    __shared__ int wsum[32];
    __shared__ int scarry;
    int t = threadIdx.x, lane = t & 31, wid = t >> 5;
    if (t == 0) scarry = 0;
    __syncthreads();
    for (int base = 0; base < NN; base += 1024) {
        int i = base + t;
        int v = (i < NN) ? g_deg[i] : 0;
        int x = v;
        #pragma unroll
        for (int d = 1; d < 32; d <<= 1) {
            int y = __shfl_up_sync(0xffffffffu, x, d);
            if (lane >= d) x += y;
        }
        if (lane == 31) wsum[wid] = x;
        __syncthreads();
        if (wid == 0) {
            int ws = wsum[lane];
            #pragma unroll
            for (int d = 1; d < 32; d <<= 1) {
                int y = __shfl_up_sync(0xffffffffu, ws, d);
                if (lane >= d) ws += y;
            }
            wsum[lane] = ws;
        }
        __syncthreads();
        int carry = scarry;
        int excl = carry + (wid ? wsum[wid - 1] : 0) + (x - v);
        if (i < NN) { g_rowp[i] = excl; g_cur[i] = excl; }
        __syncthreads();
        if (t == 0) scarry = carry + wsum[31];
        __syncthreads();
    }
    if (t == 0) g_rowp[NN] = scarry;
}
__global__ void k_dinv() {
    int i = blockIdx.x * blockDim.x + threadIdx.x;
    if (i < NN) g_dinv[i] = rsqrtf((float)(g_deg[i] + 1));
}
__global__ void k_place(const int* __restrict__ ei) {
    int e = blockIdx.x * blockDim.x + threadIdx.x;
    if (e < EE) {
        int d = ei[EE + e];
        int pos = atomicAdd(&g_cur[d], 1);
        g_esrc[pos] = ei[e];
    }
}

// ---------------- weight precompute: bf16 hi/lo, chunk-packed ----------------
template<int DIN, int DOUT, int NPAD, int NPADP>
__global__ void k_prepw(const float* __restrict__ Wb, const float* __restrict__ Ws,
                        __nv_bfloat16* __restrict__ dst) {
    constexpr int NCH = DIN * 5 / 32;
    int idx = blockIdx.x * blockDim.x + threadIdx.x;
    if (idx >= NCH * 2 * 32 * NPADP) return;
    int n = idx % NPADP;
    int k = (idx / NPADP) & 31;
    int h = (idx / (NPADP * 32)) & 1;
    int c = idx / (NPADP * 32 * 2);
    int kg = c * 32 + k;
    float w = 0.f;
    if (n < DOUT) {
        if (kg < DIN) w = Wb[(size_t)n * DIN + kg];
        else          w = Ws[(size_t)n * (DIN * 4) + (kg - DIN)];
    }
    __nv_bfloat16 hi = __float2bfloat16(w);
    __nv_bfloat16 lo = __float2bfloat16(w - __bfloat162float(hi));
    dst[idx] = h ? lo : hi;
}

// ---------------- stats of x (warp per node): mu0/rs0 + partials ----------------
__global__ void k_statx(const float* __restrict__ x) {
    int gw = (blockIdx.x * blockDim.x + threadIdx.x) >> 5;
    int lane = threadIdx.x & 31;
    if (gw >= NN) return;
    float4 v = ((const float4*)(x + (size_t)gw * 128))[lane];
    float s  = v.x + v.y + v.z + v.w;
    float s2 = v.x * v.x + v.y * v.y + v.z * v.z + v.w * v.w;
    #pragma unroll
    for (int d = 16; d; d >>= 1) {
        s  += __shfl_xor_sync(0xffffffffu, s,  d);
        s2 += __shfl_xor_sync(0xffffffffu, s2, d);
    }
    if (lane == 0) {
        float m = s * (1.f / 128.f);
        g_mu[gw] = m;
        g_rs[gw] = rsqrtf(s2 * (1.f / 128.f) - m * m + 1e-5f);
        g_sA[gw]  = s;
        g_sA2[gw] = s2;
    }
}

// ---------------- fused FastKAN layer via wmma bf16 (3-term compensation) ----------------
template<int DIN>
__device__ __forceinline__ float4 ldx4(const float* __restrict__ a,
                                       const float* __restrict__ b,
                                       const float* __restrict__ c,
                                       int n, int col) {
    if (DIN == 128) return *(const float4*)(a + (size_t)n * 128 + col);
    const float* p = (col < 128) ? a : (col < 256) ? b : c;
    return *(const float4*)(p + (size_t)n * 128 + (col & 127));
}

__device__ __forceinline__ void splitstore(__nv_bfloat16* hiP, __nv_bfloat16* loP,
                                           float4 v) {
    __nv_bfloat162 h0 = __floats2bfloat162_rn(v.x, v.y);
    __nv_bfloat162 h1 = __floats2bfloat162_rn(v.z, v.w);
    float2 f0 = __bfloat1622float2(h0);
    float2 f1 = __bfloat1622float2(h1);
    __nv_bfloat162 l0 = __floats2bfloat162_rn(v.x - f0.x, v.y - f0.y);
    __nv_bfloat162 l1 = __floats2bfloat162_rn(v.z - f1.x, v.w - f1.y);
    ((__nv_bfloat162*)hiP)[0] = h0;
    ((__nv_bfloat162*)hiP)[1] = h1;
    ((__nv_bfloat162*)loP)[0] = l0;
    ((__nv_bfloat162*)loP)[1] = l1;
}

// A smem: 128 x 40 bf16 hi + lo.  B smem: 32 x NPADP bf16 hi + lo.
// Warp grid: WM x (8/WM); each warp computes MT m-tiles x NTW n-tiles.
template<int DIN, int DOUT, int NPAD, int NPADP, int OUTP, int OUT_STRIDE, int WM>
__global__ void __launch_bounds__(256)
k_fkan_wmma(const float* __restrict__ in0, const float* __restrict__ in1,
            const float* __restrict__ in2,
            const float* __restrict__ lng, const float* __restrict__ lnb,
            const __nv_bfloat16* __restrict__ wp,
            float* __restrict__ out)
{
    constexpr int NCH = DIN * 5 / 32;
    constexpr int NT  = NPAD / 16;
    constexpr int WN  = 8 / WM;
    constexpr int MT  = 8 / WM;        // m-tiles per warp
    constexpr int NTW = NT / WN;       // n-tiles per warp
    static_assert(NT % WN == 0, "tiling");
    constexpr int ALD = 40;

    extern __shared__ char smc[];
    __nv_bfloat16* aHi = (__nv_bfloat16*)smc;             // 128*40
    __nv_bfloat16* aLo = aHi + 128 * ALD;                 // 128*40
    __nv_bfloat16* bHi = aLo + 128 * ALD;                 // 2*32*NPADP (hi then lo)
    float* sOut = (float*)smc;                            // epilogue reuse

    const int t = threadIdx.x;
    const int w = t >> 5;
    const int wm = w % WM, wn = w / WM;
    const int base = blockIdx.x * 128;

    const int r = t >> 1, half = t & 1;
    const int n = base + r;
    const bool valid = (n < NN);
    const float mu = valid ? g_mu[n] : 0.f;
    const float rs = valid ? g_rs[n] : 0.f;

    wmma::fragment<wmma::accumulator, 16, 16, 16, float> acc[MT][NTW];
    #pragma unroll
    for (int im = 0; im < MT; im++)
        #pragma unroll
        for (int in = 0; in < NTW; in++) wmma::fill_fragment(acc[im][in], 0.f);

    for (int c = 0; c < NCH; c++) {
        const int kc = c * 32;

        // ---- A staging: silu base / rbf spline, bf16 hi/lo ----
        if (kc < DIN) {
            #pragma unroll
            for (int q = 0; q < 4; q++) {
                const int c0 = half * 16 + q * 4;
                float4 xv = make_float4(0.f, 0.f, 0.f, 0.f);
                if (valid) xv = ldx4<DIN>(in0, in1, in2, n, kc + c0);
                float4 v;
                v.x = __fdividef(xv.x, 1.f + __expf(-xv.x));
                v.y = __fdividef(xv.y, 1.f + __expf(-xv.y));
                v.z = __fdividef(xv.z, 1.f + __expf(-xv.z));
                v.w = __fdividef(xv.w, 1.f + __expf(-xv.w));
                splitstore(aHi + r * ALD + c0, aLo + r * ALD + c0, v);
            }
        } else {
            const int xc = ((kc - DIN) >> 2) + half * 4;
            float4 xv = make_float4(0.f, 0.f, 0.f, 0.f);
            if (valid) xv = ldx4<DIN>(in0, in1, in2, n, xc);
            const float4 gv = *(const float4*)(lng + xc);
            const float4 bv = *(const float4*)(lnb + xc);
            float zz[4];
            zz[0] = (xv.x - mu) * rs * gv.x + bv.x;
            zz[1] = (xv.y - mu) * rs * gv.y + bv.y;
            zz[2] = (xv.z - mu) * rs * gv.z + bv.z;
            zz[3] = (xv.w - mu) * rs * gv.w + bv.w;
            #pragma unroll
            for (int i = 0; i < 4; i++) {
                float4 v;
                float u;
                u = (zz[i] + 2.f) * 0.75f;               v.x = __expf(-u * u);
                u = (zz[i] + 2.f - 4.f / 3.f) * 0.75f;   v.y = __expf(-u * u);
                u = (zz[i] + 2.f - 8.f / 3.f) * 0.75f;   v.z = __expf(-u * u);
                u = (zz[i] - 2.f) * 0.75f;               v.w = __expf(-u * u);
                const int c0 = half * 16 + i * 4;
                splitstore(aHi + r * ALD + c0, aLo + r * ALD + c0, v);
            }
        }

        // ---- B staging: straight copy of pre-split weights (hi then lo) ----
        {
            constexpr int NV4 = 2 * 32 * NPADP * 2 / 16;
            const float4* src = (const float4*)(wp + (size_t)c * (2 * 32 * NPADP));
            float4* dst = (float4*)bHi;
            #pragma unroll
            for (int i = t; i < NV4; i += 256) dst[i] = src[i];
        }
        __syncthreads();

        // ---- wmma compute: Ah*Bh + Ah*Bl + Al*Bh ----
        #pragma unroll
        for (int kk = 0; kk < 2; kk++) {
            wmma::fragment<wmma::matrix_a, 16, 16, 16, __nv_bfloat16, wmma::row_major> ah[MT], al[MT];
            #pragma unroll
            for (int im = 0; im < MT; im++) {
                const int mrow = (wm * MT + im) * 16;
                wmma::load_matrix_sync(ah[im], aHi + mrow * ALD + kk * 16, ALD);
                wmma::load_matrix_sync(al[im], aLo + mrow * ALD + kk * 16, ALD);
            }
            #pragma unroll
            for (int in = 0; in < NTW; in++) {
                const int col = (wn * NTW + in) * 16;
                wmma::fragment<wmma::matrix_b, 16, 16, 16, __nv_bfloat16, wmma::row_major> bh, bl;
                wmma::load_matrix_sync(bh, bHi + kk * 16 * NPADP + col, NPADP);
                wmma::load_matrix_sync(bl, bHi + 32 * NPADP + kk * 16 * NPADP + col, NPADP);
                #pragma unroll
                for (int im = 0; im < MT; im++) {
                    wmma::mma_sync(acc[im][in], ah[im], bh, acc[im][in]);
                    wmma::mma_sync(acc[im][in], ah[im], bl, acc[im][in]);
                    wmma::mma_sync(acc[im][in], al[im], bh, acc[im][in]);
                }
            }
        }
        __syncthreads();
    }

    // ---- epilogue: accs -> smem -> guarded global store (bias folded into agg) ----
    #pragma unroll
    for (int im = 0; im < MT; im++)
        #pragma unroll
        for (int in = 0; in < NTW; in++)
            wmma::store_matrix_sync(
                sOut + ((wm * MT + im) * 16) * OUTP + (wn * NTW + in) * 16,
                acc[im][in], OUTP, wmma::mem_row_major);
    __syncthreads();

    if (NPAD == 128) {
        for (int e = t; e < 128 * 32; e += 256) {
            int rr = e >> 5, c4 = e & 31;
            int n2 = base + rr;
            if (n2 < NN)
                ((float4*)(out + (size_t)n2 * OUT_STRIDE))[c4] =
                    *(float4*)&sOut[rr * OUTP + c4 * 4];
        }
    } else {
        for (int e = t; e < 128 * NPAD; e += 256) {
            int rr = e / NPAD, o = e % NPAD;
            int n2 = base + rr;
            if (o < DOUT && n2 < NN)
                out[(size_t)n2 * OUT_STRIDE + o] = sOut[rr * OUTP + o];
        }
    }
}

// ---------------- aggregation + fused layernorm stats ----------------
// statmode 1: write mu/rs from this output (din=128); g_sA += s (partials for layer2)
// statmode 2: write mu/rs over concat (din=384) using stored partials
__global__ void k_agg128(const float* __restrict__ tin, float* __restrict__ outp,
                         const float* __restrict__ bs, const float* __restrict__ bb,
                         const float* __restrict__ bg, int statmode) {
    int gw = (blockIdx.x * blockDim.x + threadIdx.x) >> 5;
    int lane = threadIdx.x & 31;
    if (gw >= NN) return;
    int beg = g_rowp[gw], end = g_rowp[gw + 1];
    const float4* t4 = (const float4*)tin;
    float4 a = make_float4(0.f, 0.f, 0.f, 0.f);
    float sw = 0.f;
    int j = beg;
    for (; j + 1 < end; j += 2) {
        int s0 = g_esrc[j], s1 = g_esrc[j + 1];
        float w0 = g_dinv[s0], w1 = g_dinv[s1];
        sw += w0 + w1;
        float4 v0 = t4[(size_t)s0 * 32 + lane];
        float4 v1 = t4[(size_t)s1 * 32 + lane];
        a.x += w0 * v0.x + w1 * v1.x;
        a.y += w0 * v0.y + w1 * v1.y;
        a.z += w0 * v0.z + w1 * v1.z;
        a.w += w0 * v0.w + w1 * v1.w;
    }
    if (j < end) {
        int s0 = g_esrc[j];
        float w0 = g_dinv[s0];
        sw += w0;
        float4 v0 = t4[(size_t)s0 * 32 + lane];
        a.x += w0 * v0.x; a.y += w0 * v0.y; a.z += w0 * v0.z; a.w += w0 * v0.w;
    }
    float dn = g_dinv[gw];
    float wb = dn * (sw + dn);   // bias weight: sum of norms incl self
    float4 sv = t4[(size_t)gw * 32 + lane];
    float4 bgv = ((const float4*)bg)[lane];
    float4 bsv = ((const float4*)bs)[lane];
    float4 bbv = ((const float4*)bb)[lane];
    float4 o;
    o.x = dn * (a.x + dn * sv.x) + (bsv.x + bbv.x) * wb + bgv.x;
    o.y = dn * (a.y + dn * sv.y) + (bsv.y + bbv.y) * wb + bgv.y;
    o.z = dn * (a.z + dn * sv.z) + (bsv.z + bbv.z) * wb + bgv.z;
    o.w = dn * (a.w + dn * sv.w) + (bsv.w + bbv.w) * wb + bgv.w;
    ((float4*)outp)[(size_t)gw * 32 + lane] = o;

    // fused layernorm stats for next layer
    float s  = o.x + o.y + o.z + o.w;
    float s2 = o.x * o.x + o.y * o.y + o.z * o.z + o.w * o.w;
    #pragma unroll
    for (int d = 16; d; d >>= 1) {
        s  += __shfl_xor_sync(0xffffffffu, s,  d);
        s2 += __shfl_xor_sync(0xffffffffu, s2, d);
    }
    if (lane == 0) {
        if (statmode == 1) {
            float m = s * (1.f / 128.f);
            g_mu[gw] = m;
            g_rs[gw] = rsqrtf(s2 * (1.f / 128.f) - m * m + 1e-5f);
            g_sA[gw]  += s;     // accumulate x-partials -> x + h1
            g_sA2[gw] += s2;
        } else {
            float ts  = g_sA[gw]  + s;
            float ts2 = g_sA2[gw] + s2;
            float m = ts * (1.f / 384.f);
            g_mu[gw] = m;
            g_rs[gw] = rsqrtf(ts2 * (1.f / 384.f) - m * m + 1e-5f);
        }
    }
}

__global__ void k_agg47(const float* __restrict__ tin, float* __restrict__ outp,
                        const float* __restrict__ bs, const float* __restrict__ bb,
                        const float* __restrict__ bg) {
    int gw = (blockIdx.x * blockDim.x + threadIdx.x) >> 5;
    int lane = threadIdx.x & 31;
    if (gw >= NN) return;
    int beg = g_rowp[gw], end = g_rowp[gw + 1];
    float a0 = 0.f, a1 = 0.f, sw = 0.f;
    for (int j = beg; j < end; j++) {
        int s = g_esrc[j];
        float w = g_dinv[s];
        sw += w;
        const float* ts = tin + (size_t)s * 64;
        a0 += w * ts[lane];
        if (lane < 15) a1 += w * ts[32 + lane];
    }
    float dn = g_dinv[gw];
    float wb = dn * (sw + dn);
    const float* tn = tin + (size_t)gw * 64;
    outp[(size_t)gw * 47 + lane] =
        dn * (a0 + dn * tn[lane]) + (bs[lane] + bb[lane]) * wb + bg[lane];
    if (lane < 15)
        outp[(size_t)gw * 47 + 32 + lane] =
            dn * (a1 + dn * tn[32 + lane]) + (bs[32 + lane] + bb[32 + lane]) * wb + bg[32 + lane];
}

// ---------------- driver ----------------
extern "C" void kernel_launch(void* const* d_in, const int* in_sizes, int n_in,
                              void* d_out, int out_size) {
    const float* x    = (const float*)d_in[0];
    const int*   ei   = (const int*)d_in[1];
    const float* lng0 = (const float*)d_in[2];
    const float* lnb0 = (const float*)d_in[3];
    const float* Ws0  = (const float*)d_in[4];
    const float* bs0  = (const float*)d_in[5];
    const float* Wb0  = (const float*)d_in[6];
    const float* bb0  = (const float*)d_in[7];
    const float* bg0  = (const float*)d_in[8];
    const float* lng1 = (const float*)d_in[9];
    const float* lnb1 = (const float*)d_in[10];
    const float* Ws1  = (const float*)d_in[11];
    const float* bs1  = (const float*)d_in[12];
    const float* Wb1  = (const float*)d_in[13];
    const float* bb1  = (const float*)d_in[14];
    const float* bg1  = (const float*)d_in[15];
    const float* lng2 = (const float*)d_in[16];
    const float* lnb2 = (const float*)d_in[17];
    const float* Ws2  = (const float*)d_in[18];
    const float* bs2  = (const float*)d_in[19];
    const float* Wb2  = (const float*)d_in[20];
    const float* bb2  = (const float*)d_in[21];
    const float* bg2  = (const float*)d_in[22];
    float* outp = (float*)d_out;

    void *pt, *ph1, *ph2, *pt2, *pw0, *pw1, *pw2;
    cudaGetSymbolAddress(&pt,  g_t);
    cudaGetSymbolAddress(&ph1, g_h1);
    cudaGetSymbolAddress(&ph2, g_h2);
    cudaGetSymbolAddress(&pt2, g_t2);
    cudaGetSymbolAddress(&pw0, g_wb0);
    cudaGetSymbolAddress(&pw1, g_wb1);
    cudaGetSymbolAddress(&pw2, g_wb2);

    const int SM_L01 = 128 * 132 * 4;                       // 67584 (epilogue)
    const int SM_L2  = 2 * 128 * 40 * 2 + 2 * 32 * 56 * 2;  // 27648 (staging)
    cudaFuncSetAttribute((const void*)k_fkan_wmma<128, 128, 128, 136, 132, 128, 4>,
                         cudaFuncAttributeMaxDynamicSharedMemorySize, SM_L01);
    cudaFuncSetAttribute((const void*)k_fkan_wmma<384, 47, 48, 56, 52, 64, 8>,
                         cudaFuncAttributeMaxDynamicSharedMemorySize, SM_L2);

    // graph preprocessing -> CSR + dinv
    k_zero_deg<<<(NN + 255) / 256, 256>>>();
    k_count<<<(EE + 255) / 256, 256>>>(ei);
    k_scan<<<1, 1024>>>();
    k_dinv<<<(NN + 255) / 256, 256>>>();
    k_place<<<(EE + 255) / 256, 256>>>(ei);

    // weight precompute (bf16 split, chunk-packed)
    k_prepw<128, 128, 128, 136><<<(20 * 2 * 32 * 136 + 255) / 256, 256>>>(
        Wb0, Ws0, (__nv_bfloat16*)pw0);
    k_prepw<128, 128, 128, 136><<<(20 * 2 * 32 * 136 + 255) / 256, 256>>>(
        Wb1, Ws1, (__nv_bfloat16*)pw1);
    k_prepw<384, 47, 48, 56><<<(60 * 2 * 32 * 56 + 255) / 256, 256>>>(
        Wb2, Ws2, (__nv_bfloat16*)pw2);

    const int FG = (NN + 127) / 128;          // 782
    const int SG = (NN * 32 + 255) / 256;     // warp per node

    // layer 0 (stats of x -> mu0/rs0 + partials)
    k_statx<<<SG, 256>>>(x);
    k_fkan_wmma<128, 128, 128, 136, 132, 128, 4><<<FG, 256, SM_L01>>>(
        x, nullptr, nullptr, lng0, lnb0, (const __nv_bfloat16*)pw0, (float*)pt);
    k_agg128<<<SG, 256>>>((const float*)pt, (float*)ph1, bs0, bb0, bg0, 1);

    // layer 1 (mu1/rs1 written by previous agg)
    k_fkan_wmma<128, 128, 128, 136, 132, 128, 4><<<FG, 256, SM_L01>>>(
        (const float*)ph1, nullptr, nullptr, lng1, lnb1, (const __nv_bfloat16*)pw1,
        (float*)pt);
    k_agg128<<<SG, 256>>>((const float*)pt, (float*)ph2, bs1, bb1, bg1, 2);

    // layer 2 (mu2/rs2 over concat written by previous agg)
    k_fkan_wmma<384, 47, 48, 56, 52, 64, 8><<<FG, 256, SM_L2>>>(
        x, (const float*)ph1, (const float*)ph2, lng2, lnb2,
        (const __nv_bfloat16*)pw2, (float*)pt2);
    k_agg47<<<SG, 256>>>((const float*)pt2, outp, bs2, bb2, bg2);
}

// round 7
// speedup vs baseline: 2.9600x; 1.0851x over previous
#include <cuda_runtime.h>
#include <cuda_bf16.h>
#include <mma.h>
#include <cstdint>
#include <math.h>

using namespace nvcuda;

#define NN 100000
#define EE 1600000

// ---------------- scratch (device globals; no runtime allocation) ----------------
__device__ int   g_deg[NN];
__device__ int   g_rowp[NN + 1];
__device__ int   g_cur[NN];
__device__ int   g_esrc[EE];
__device__ float g_dinv[NN];
__device__ float g_mu[NN];
__device__ float g_rs[NN];
__device__ float g_sA[NN];    // running partial sum   (x, then x+h1)
__device__ float g_sA2[NN];   // running partial sumsq
__device__ float g_t [NN * 128];
__device__ float g_h1[NN * 128];
__device__ float g_h2[NN * 128];
__device__ float g_t2[NN * 64];
// packed bf16-split weights: per chunk [hi 32*NPADP][lo 32*NPADP]
__device__ __align__(16) __nv_bfloat16 g_wb0[20 * 2 * 32 * 136];
__device__ __align__(16) __nv_bfloat16 g_wb1[20 * 2 * 32 * 136];
__device__ __align__(16) __nv_bfloat16 g_wb2[60 * 2 * 32 * 56];

// ---------------- async-copy helpers ----------------
__device__ __forceinline__ uint32_t smem_u32(const void* p) {
    uint32_t a;
    asm("{ .reg .u64 t; cvta.to.shared.u64 t, %1; cvt.u32.u64 %0, t; }"
        : "=r"(a) : "l"(p));
    return a;
}
__device__ __forceinline__ void cpasync16(uint32_t dst, const void* src) {
    asm volatile("cp.async.cg.shared.global [%0], [%1], 16;" :: "r"(dst), "l"(src));
}
#define CPCOMMIT() asm volatile("cp.async.commit_group;" ::: "memory")
#define CPWAIT0()  asm volatile("cp.async.wait_group 0;" ::: "memory")

// ---------------- graph preprocessing ----------------
__global__ void k_zero_deg() {
    int i = blockIdx.x * blockDim.x + threadIdx.x;
    if (i < NN) g_deg[i] = 0;
}
__global__ void k_count(const int* __restrict__ ei) {
    int e = blockIdx.x * blockDim.x + threadIdx.x;
    if (e < EE) atomicAdd(&g_deg[ei[EE + e]], 1);
}
__global__ void k_scan() {
    __shared__ int wsum[32];
    __shared__ int scarry;
    int t = threadIdx.x, lane = t & 31, wid = t >> 5;
    if (t == 0) scarry = 0;
    __syncthreads();
    for (int base = 0; base < NN; base += 1024) {
        int i = base + t;
        int v = (i < NN) ? g_deg[i] : 0;
        int x = v;
        #pragma unroll
        for (int d = 1; d < 32; d <<= 1) {
            int y = __shfl_up_sync(0xffffffffu, x, d);
            if (lane >= d) x += y;
        }
        if (lane == 31) wsum[wid] = x;
        __syncthreads();
        if (wid == 0) {
            int ws = wsum[lane];
            #pragma unroll
            for (int d = 1; d < 32; d <<= 1) {
                int y = __shfl_up_sync(0xffffffffu, ws, d);
                if (lane >= d) ws += y;
            }
            wsum[lane] = ws;
        }
        __syncthreads();
        int carry = scarry;
        int excl = carry + (wid ? wsum[wid - 1] : 0) + (x - v);
        if (i < NN) { g_rowp[i] = excl; g_cur[i] = excl; }
        __syncthreads();
        if (t == 0) scarry = carry + wsum[31];
        __syncthreads();
    }
    if (t == 0) g_rowp[NN] = scarry;
}
__global__ void k_dinv() {
    int i = blockIdx.x * blockDim.x + threadIdx.x;
    if (i < NN) g_dinv[i] = rsqrtf((float)(g_deg[i] + 1));
}
__global__ void k_place(const int* __restrict__ ei) {
    int e = blockIdx.x * blockDim.x + threadIdx.x;
    if (e < EE) {
        int d = ei[EE + e];
        int pos = atomicAdd(&g_cur[d], 1);
        g_esrc[pos] = ei[e];
    }
}

// ---------------- weight precompute: bf16 hi/lo, chunk-packed ----------------
template<int DIN, int DOUT, int NPAD, int NPADP>
__global__ void k_prepw(const float* __restrict__ Wb, const float* __restrict__ Ws,
                        __nv_bfloat16* __restrict__ dst) {
    constexpr int NCH = DIN * 5 / 32;
    int idx = blockIdx.x * blockDim.x + threadIdx.x;
    if (idx >= NCH * 2 * 32 * NPADP) return;
    int n = idx % NPADP;
    int k = (idx / NPADP) & 31;
    int h = (idx / (NPADP * 32)) & 1;
    int c = idx / (NPADP * 32 * 2);
    int kg = c * 32 + k;
    float w = 0.f;
    if (n < DOUT) {
        if (kg < DIN) w = Wb[(size_t)n * DIN + kg];
        else          w = Ws[(size_t)n * (DIN * 4) + (kg - DIN)];
    }
    __nv_bfloat16 hi = __float2bfloat16(w);
    __nv_bfloat16 lo = __float2bfloat16(w - __bfloat162float(hi));
    dst[idx] = h ? lo : hi;
}

// ---------------- stats of x (warp per node): mu0/rs0 + partials ----------------
__global__ void k_statx(const float* __restrict__ x) {
    int gw = (blockIdx.x * blockDim.x + threadIdx.x) >> 5;
    int lane = threadIdx.x & 31;
    if (gw >= NN) return;
    float4 v = ((const float4*)(x + (size_t)gw * 128))[lane];
    float s  = v.x + v.y + v.z + v.w;
    float s2 = v.x * v.x + v.y * v.y + v.z * v.z + v.w * v.w;
    #pragma unroll
    for (int d = 16; d; d >>= 1) {
        s  += __shfl_xor_sync(0xffffffffu, s,  d);
        s2 += __shfl_xor_sync(0xffffffffu, s2, d);
    }
    if (lane == 0) {
        float m = s * (1.f / 128.f);
        g_mu[gw] = m;
        g_rs[gw] = rsqrtf(s2 * (1.f / 128.f) - m * m + 1e-5f);
        g_sA[gw]  = s;
        g_sA2[gw] = s2;
    }
}

// ---------------- fused FastKAN layer via wmma bf16 (3-term compensation) ----------------
template<int DIN>
__device__ __forceinline__ float4 ldx4(const float* __restrict__ a,
                                       const float* __restrict__ b,
                                       const float* __restrict__ c,
                                       int n, int col) {
    if (DIN == 128) return *(const float4*)(a + (size_t)n * 128 + col);
    const float* p = (col < 128) ? a : (col < 256) ? b : c;
    return *(const float4*)(p + (size_t)n * 128 + (col & 127));
}

__device__ __forceinline__ void splitstore(__nv_bfloat16* hiP, __nv_bfloat16* loP,
                                           float4 v) {
    __nv_bfloat162 h0 = __floats2bfloat162_rn(v.x, v.y);
    __nv_bfloat162 h1 = __floats2bfloat162_rn(v.z, v.w);
    float2 f0 = __bfloat1622float2(h0);
    float2 f1 = __bfloat1622float2(h1);
    __nv_bfloat162 l0 = __floats2bfloat162_rn(v.x - f0.x, v.y - f0.y);
    __nv_bfloat162 l1 = __floats2bfloat162_rn(v.z - f1.x, v.w - f1.y);
    ((__nv_bfloat162*)hiP)[0] = h0;
    ((__nv_bfloat162*)hiP)[1] = h1;
    ((__nv_bfloat162*)loP)[0] = l0;
    ((__nv_bfloat162*)loP)[1] = l1;
}

// Double-buffered stages: [aHi 128*ALD][aLo 128*ALD][B hi+lo 2*32*NPADP] per stage.
template<int DIN, int DOUT, int NPAD, int NPADP, int OUTP, int OUT_STRIDE, int WM>
__global__ void __launch_bounds__(256)
k_fkan_wmma(const float* __restrict__ in0, const float* __restrict__ in1,
            const float* __restrict__ in2,
            const float* __restrict__ lng, const float* __restrict__ lnb,
            const __nv_bfloat16* __restrict__ wp,
            float* __restrict__ out)
{
    constexpr int NCH = DIN * 5 / 32;
    constexpr int NT  = NPAD / 16;
    constexpr int WN  = 8 / WM;
    constexpr int MT  = 8 / WM;
    constexpr int NTW = NT / WN;
    static_assert(NT % WN == 0, "tiling");
    constexpr int ALD = 40;
    constexpr int AELE = 128 * ALD;                   // elements per A plane
    constexpr int BELE = 2 * 32 * NPADP;              // hi+lo B elements per chunk
    constexpr int SELE = 2 * AELE + BELE;             // elements per stage

    extern __shared__ char smc[];
    __nv_bfloat16* sb16 = (__nv_bfloat16*)smc;
    const uint32_t sbase = smem_u32(smc);
    float* sOut = (float*)smc;                        // epilogue reuse

    const int t = threadIdx.x;
    const int w = t >> 5;
    const int wm = w % WM, wn = w / WM;
    const int base = blockIdx.x * 128;

    const int r = t >> 1, half = t & 1;
    const int n = base + r;
    const bool valid = (n < NN);
    const float mu = valid ? g_mu[n] : 0.f;
    const float rs = valid ? g_rs[n] : 0.f;

    wmma::fragment<wmma::accumulator, 16, 16, 16, float> acc[MT][NTW];
    #pragma unroll
    for (int im = 0; im < MT; im++)
        #pragma unroll
        for (int in = 0; in < NTW; in++) wmma::fill_fragment(acc[im][in], 0.f);

    // --- staging lambdas ---
    auto stageA = [&](int c, int s) {
        __nv_bfloat16* aHi = sb16 + s * SELE;
        __nv_bfloat16* aLo = aHi + AELE;
        const int kc = c * 32;
        if (kc < DIN) {
            #pragma unroll
            for (int q = 0; q < 4; q++) {
                const int c0 = half * 16 + q * 4;
                float4 xv = make_float4(0.f, 0.f, 0.f, 0.f);
                if (valid) xv = ldx4<DIN>(in0, in1, in2, n, kc + c0);
                float4 v;
                v.x = __fdividef(xv.x, 1.f + __expf(-xv.x));
                v.y = __fdividef(xv.y, 1.f + __expf(-xv.y));
                v.z = __fdividef(xv.z, 1.f + __expf(-xv.z));
                v.w = __fdividef(xv.w, 1.f + __expf(-xv.w));
                splitstore(aHi + r * ALD + c0, aLo + r * ALD + c0, v);
            }
        } else {
            const int xc = ((kc - DIN) >> 2) + half * 4;
            float4 xv = make_float4(0.f, 0.f, 0.f, 0.f);
            if (valid) xv = ldx4<DIN>(in0, in1, in2, n, xc);
            const float4 gv = *(const float4*)(lng + xc);
            const float4 bv = *(const float4*)(lnb + xc);
            float zz[4];
            zz[0] = (xv.x - mu) * rs * gv.x + bv.x;
            zz[1] = (xv.y - mu) * rs * gv.y + bv.y;
            zz[2] = (xv.z - mu) * rs * gv.z + bv.z;
            zz[3] = (xv.w - mu) * rs * gv.w + bv.w;
            #pragma unroll
            for (int i = 0; i < 4; i++) {
                float4 v;
                float u;
                u = (zz[i] + 2.f) * 0.75f;               v.x = __expf(-u * u);
                u = (zz[i] + 2.f - 4.f / 3.f) * 0.75f;   v.y = __expf(-u * u);
                u = (zz[i] + 2.f - 8.f / 3.f) * 0.75f;   v.z = __expf(-u * u);
                u = (zz[i] - 2.f) * 0.75f;               v.w = __expf(-u * u);
                const int c0 = half * 16 + i * 4;
                splitstore(aHi + r * ALD + c0, aLo + r * ALD + c0, v);
            }
        }
    };
    auto stageB = [&](int c, int s) {
        constexpr int NV4 = BELE * 2 / 16;            // 16B transfers
        const char* src = (const char*)(wp + (size_t)c * BELE);
        const uint32_t dst = sbase + (s * SELE + 2 * AELE) * 2;
        #pragma unroll
        for (int i = t; i < NV4; i += 256)
            cpasync16(dst + i * 16, src + i * 16);
    };

    // --- prologue ---
    stageB(0, 0);
    CPCOMMIT();
    stageA(0, 0);
    CPWAIT0();
    __syncthreads();

    for (int c = 0; c < NCH; c++) {
        const int s = c & 1;
        if (c + 1 < NCH) { stageB(c + 1, 1 - s); CPCOMMIT(); }

        // ---- wmma compute on stage s: Ah*Bh + Ah*Bl + Al*Bh ----
        {
            __nv_bfloat16* aHi = sb16 + s * SELE;
            __nv_bfloat16* aLo = aHi + AELE;
            __nv_bfloat16* bHi = aLo + AELE;
            #pragma unroll
            for (int kk = 0; kk < 2; kk++) {
                wmma::fragment<wmma::matrix_a, 16, 16, 16, __nv_bfloat16, wmma::row_major> ah[MT], al[MT];
                #pragma unroll
                for (int im = 0; im < MT; im++) {
                    const int mrow = (wm * MT + im) * 16;
                    wmma::load_matrix_sync(ah[im], aHi + mrow * ALD + kk * 16, ALD);
                    wmma::load_matrix_sync(al[im], aLo + mrow * ALD + kk * 16, ALD);
                }
                #pragma unroll
                for (int in = 0; in < NTW; in++) {
                    const int col = (wn * NTW + in) * 16;
                    wmma::fragment<wmma::matrix_b, 16, 16, 16, __nv_bfloat16, wmma::row_major> bh, bl;
                    wmma::load_matrix_sync(bh, bHi + kk * 16 * NPADP + col, NPADP);
                    wmma::load_matrix_sync(bl, bHi + 32 * NPADP + kk * 16 * NPADP + col, NPADP);
                    #pragma unroll
                    for (int im = 0; im < MT; im++) {
                        wmma::mma_sync(acc[im][in], ah[im], bh, acc[im][in]);
                        wmma::mma_sync(acc[im][in], ah[im], bl, acc[im][in]);
                        wmma::mma_sync(acc[im][in], al[im], bh, acc[im][in]);
                    }
                }
            }
        }

        if (c + 1 < NCH) stageA(c + 1, 1 - s);
        CPWAIT0();
        __syncthreads();
    }

    // ---- epilogue: accs -> smem -> guarded global store (bias folded into agg) ----
    #pragma unroll
    for (int im = 0; im < MT; im++)
        #pragma unroll
        for (int in = 0; in < NTW; in++)
            wmma::store_matrix_sync(
                sOut + ((wm * MT + im) * 16) * OUTP + (wn * NTW + in) * 16,
                acc[im][in], OUTP, wmma::mem_row_major);
    __syncthreads();

    if (NPAD == 128) {
        for (int e = t; e < 128 * 32; e += 256) {
            int rr = e >> 5, c4 = e & 31;
            int n2 = base + rr;
            if (n2 < NN)
                ((float4*)(out + (size_t)n2 * OUT_STRIDE))[c4] =
                    *(float4*)&sOut[rr * OUTP + c4 * 4];
        }
    } else {
        for (int e = t; e < 128 * NPAD; e += 256) {
            int rr = e / NPAD, o = e % NPAD;
            int n2 = base + rr;
            if (o < DOUT && n2 < NN)
                out[(size_t)n2 * OUT_STRIDE + o] = sOut[rr * OUTP + o];
        }
    }
}

// ---------------- aggregation + fused layernorm stats ----------------
__global__ void k_agg128(const float* __restrict__ tin, float* __restrict__ outp,
                         const float* __restrict__ bs, const float* __restrict__ bb,
                         const float* __restrict__ bg, int statmode) {
    int gw = (blockIdx.x * blockDim.x + threadIdx.x) >> 5;
    int lane = threadIdx.x & 31;
    if (gw >= NN) return;
    int beg = g_rowp[gw], end = g_rowp[gw + 1];
    const float4* t4 = (const float4*)tin;
    float4 a = make_float4(0.f, 0.f, 0.f, 0.f);
    float sw = 0.f;
    int j = beg;
    for (; j + 1 < end; j += 2) {
        int s0 = g_esrc[j], s1 = g_esrc[j + 1];
        float w0 = g_dinv[s0], w1 = g_dinv[s1];
        sw += w0 + w1;
        float4 v0 = t4[(size_t)s0 * 32 + lane];
        float4 v1 = t4[(size_t)s1 * 32 + lane];
        a.x += w0 * v0.x + w1 * v1.x;
        a.y += w0 * v0.y + w1 * v1.y;
        a.z += w0 * v0.z + w1 * v1.z;
        a.w += w0 * v0.w + w1 * v1.w;
    }
    if (j < end) {
        int s0 = g_esrc[j];
        float w0 = g_dinv[s0];
        sw += w0;
        float4 v0 = t4[(size_t)s0 * 32 + lane];
        a.x += w0 * v0.x; a.y += w0 * v0.y; a.z += w0 * v0.z; a.w += w0 * v0.w;
    }
    float dn = g_dinv[gw];
    float wb = dn * (sw + dn);
    float4 sv = t4[(size_t)gw * 32 + lane];
    float4 bgv = ((const float4*)bg)[lane];
    float4 bsv = ((const float4*)bs)[lane];
    float4 bbv = ((const float4*)bb)[lane];
    float4 o;
    o.x = dn * (a.x + dn * sv.x) + (bsv.x + bbv.x) * wb + bgv.x;
    o.y = dn * (a.y + dn * sv.y) + (bsv.y + bbv.y) * wb + bgv.y;
    o.z = dn * (a.z + dn * sv.z) + (bsv.z + bbv.z) * wb + bgv.z;
    o.w = dn * (a.w + dn * sv.w) + (bsv.w + bbv.w) * wb + bgv.w;
    ((float4*)outp)[(size_t)gw * 32 + lane] = o;

    float s  = o.x + o.y + o.z + o.w;
    float s2 = o.x * o.x + o.y * o.y + o.z * o.z + o.w * o.w;
    #pragma unroll
    for (int d = 16; d; d >>= 1) {
        s  += __shfl_xor_sync(0xffffffffu, s,  d);
        s2 += __shfl_xor_sync(0xffffffffu, s2, d);
    }
    if (lane == 0) {
        if (statmode == 1) {
            float m = s * (1.f / 128.f);
            g_mu[gw] = m;
            g_rs[gw] = rsqrtf(s2 * (1.f / 128.f) - m * m + 1e-5f);
            g_sA[gw]  += s;
            g_sA2[gw] += s2;
        } else {
            float ts  = g_sA[gw]  + s;
            float ts2 = g_sA2[gw] + s2;
            float m = ts * (1.f / 384.f);
            g_mu[gw] = m;
            g_rs[gw] = rsqrtf(ts2 * (1.f / 384.f) - m * m + 1e-5f);
        }
    }
}

__global__ void k_agg47(const float* __restrict__ tin, float* __restrict__ outp,
                        const float* __restrict__ bs, const float* __restrict__ bb,
                        const float* __restrict__ bg) {
    int gw = (blockIdx.x * blockDim.x + threadIdx.x) >> 5;
    int lane = threadIdx.x & 31;
    if (gw >= NN) return;
    int beg = g_rowp[gw], end = g_rowp[gw + 1];
    float a0 = 0.f, a1 = 0.f, sw = 0.f;
    for (int j = beg; j < end; j++) {
        int s = g_esrc[j];
        float w = g_dinv[s];
        sw += w;
        const float* ts = tin + (size_t)s * 64;
        a0 += w * ts[lane];
        if (lane < 15) a1 += w * ts[32 + lane];
    }
    float dn = g_dinv[gw];
    float wb = dn * (sw + dn);
    const float* tn = tin + (size_t)gw * 64;
    outp[(size_t)gw * 47 + lane] =
        dn * (a0 + dn * tn[lane]) + (bs[lane] + bb[lane]) * wb + bg[lane];
    if (lane < 15)
        outp[(size_t)gw * 47 + 32 + lane] =
            dn * (a1 + dn * tn[32 + lane]) + (bs[32 + lane] + bb[32 + lane]) * wb + bg[32 + lane];
}

// ---------------- driver ----------------
extern "C" void kernel_launch(void* const* d_in, const int* in_sizes, int n_in,
                              void* d_out, int out_size) {
    const float* x    = (const float*)d_in[0];
    const int*   ei   = (const int*)d_in[1];
    const float* lng0 = (const float*)d_in[2];
    const float* lnb0 = (const float*)d_in[3];
    const float* Ws0  = (const float*)d_in[4];
    const float* bs0  = (const float*)d_in[5];
    const float* Wb0  = (const float*)d_in[6];
    const float* bb0  = (const float*)d_in[7];
    const float* bg0  = (const float*)d_in[8];
    const float* lng1 = (const float*)d_in[9];
    const float* lnb1 = (const float*)d_in[10];
    const float* Ws1  = (const float*)d_in[11];
    const float* bs1  = (const float*)d_in[12];
    const float* Wb1  = (const float*)d_in[13];
    const float* bb1  = (const float*)d_in[14];
    const float* bg1  = (const float*)d_in[15];
    const float* lng2 = (const float*)d_in[16];
    const float* lnb2 = (const float*)d_in[17];
    const float* Ws2  = (const float*)d_in[18];
    const float* bs2  = (const float*)d_in[19];
    const float* Wb2  = (const float*)d_in[20];
    const float* bb2  = (const float*)d_in[21];
    const float* bg2  = (const float*)d_in[22];
    float* outp = (float*)d_out;

    void *pt, *ph1, *ph2, *pt2, *pw0, *pw1, *pw2;
    cudaGetSymbolAddress(&pt,  g_t);
    cudaGetSymbolAddress(&ph1, g_h1);
    cudaGetSymbolAddress(&ph2, g_h2);
    cudaGetSymbolAddress(&pt2, g_t2);
    cudaGetSymbolAddress(&pw0, g_wb0);
    cudaGetSymbolAddress(&pw1, g_wb1);
    cudaGetSymbolAddress(&pw2, g_wb2);

    // stage = 2*128*40*2 + 2*32*NPADP*2 bytes
    const int SM_L01 = 2 * (2 * 128 * 40 * 2 + 2 * 32 * 136 * 2);  // 75776
    const int SM_L2  = 2 * (2 * 128 * 40 * 2 + 2 * 32 * 56 * 2);   // 55296
    cudaFuncSetAttribute((const void*)k_fkan_wmma<128, 128, 128, 136, 132, 128, 4>,
                         cudaFuncAttributeMaxDynamicSharedMemorySize, SM_L01);
    cudaFuncSetAttribute((const void*)k_fkan_wmma<384, 47, 48, 56, 52, 64, 8>,
                         cudaFuncAttributeMaxDynamicSharedMemorySize, SM_L2);

    const int FG = (NN + 127) / 128;          // 782
    const int SG = (NN * 32 + 255) / 256;     // warp per node

    // launches 1-5 (so launch #6 is the big fkan kernel for ncu -s 5 -c 1)
    k_statx<<<SG, 256>>>(x);
    k_prepw<128, 128, 128, 136><<<(20 * 2 * 32 * 136 + 255) / 256, 256>>>(
        Wb0, Ws0, (__nv_bfloat16*)pw0);
    k_prepw<128, 128, 128, 136><<<(20 * 2 * 32 * 136 + 255) / 256, 256>>>(
        Wb1, Ws1, (__nv_bfloat16*)pw1);
    k_prepw<384, 47, 48, 56><<<(60 * 2 * 32 * 56 + 255) / 256, 256>>>(
        Wb2, Ws2, (__nv_bfloat16*)pw2);
    k_zero_deg<<<(NN + 255) / 256, 256>>>();

    // launch #6: layer-0 fkan (profiled)
    k_fkan_wmma<128, 128, 128, 136, 132, 128, 4><<<FG, 256, SM_L01>>>(
        x, nullptr, nullptr, lng0, lnb0, (const __nv_bfloat16*)pw0, (float*)pt);

    // graph preprocessing -> CSR + dinv (overlaps conceptually; stream-serial anyway)
    k_count<<<(EE + 255) / 256, 256>>>(ei);
    k_scan<<<1, 1024>>>();
    k_dinv<<<(NN + 255) / 256, 256>>>();
    k_place<<<(EE + 255) / 256, 256>>>(ei);

    k_agg128<<<SG, 256>>>((const float*)pt, (float*)ph1, bs0, bb0, bg0, 1);

    // layer 1
    k_fkan_wmma<128, 128, 128, 136, 132, 128, 4><<<FG, 256, SM_L01>>>(
        (const float*)ph1, nullptr, nullptr, lng1, lnb1, (const __nv_bfloat16*)pw1,
        (float*)pt);
    k_agg128<<<SG, 256>>>((const float*)pt, (float*)ph2, bs1, bb1, bg1, 2);

    // layer 2
    k_fkan_wmma<384, 47, 48, 56, 52, 64, 8><<<FG, 256, SM_L2>>>(
        x, (const float*)ph1, (const float*)ph2, lng2, lnb2,
        (const __nv_bfloat16*)pw2, (float*)pt2);
    k_agg47<<<SG, 256>>>((const float*)pt2, outp, bs2, bb2, bg2);
}

// round 8
// speedup vs baseline: 3.0968x; 1.0462x over previous
#include <cuda_runtime.h>
#include <cuda_bf16.h>
#include <mma.h>
#include <cstdint>
#include <math.h>

using namespace nvcuda;

#define NN 100000
#define EE 1600000

// ---------------- scratch (device globals; no runtime allocation) ----------------
__device__ int   g_deg[NN];
__device__ int   g_rowp[NN + 1];
__device__ int   g_cur[NN];
__device__ int   g_esrc[EE];
__device__ float g_dinv[NN];
__device__ float g_mu[NN];
__device__ float g_rs[NN];
__device__ float g_sA[NN];
__device__ float g_sA2[NN];
__device__ float g_t [NN * 128];
__device__ float g_h1[NN * 128];
__device__ float g_h2[NN * 128];
__device__ float g_t2[NN * 64];
// packed bf16-split weights: per chunk [hi 32*NPADP][lo 32*NPADP]
__device__ __align__(16) __nv_bfloat16 g_wb0[20 * 2 * 32 * 136];
__device__ __align__(16) __nv_bfloat16 g_wb1[20 * 2 * 32 * 136];
__device__ __align__(16) __nv_bfloat16 g_wb2[60 * 2 * 32 * 56];

// ---------------- async-copy helpers ----------------
__device__ __forceinline__ uint32_t smem_u32(const void* p) {
    uint32_t a;
    asm("{ .reg .u64 t; cvta.to.shared.u64 t, %1; cvt.u32.u64 %0, t; }"
        : "=r"(a) : "l"(p));
    return a;
}
__device__ __forceinline__ void cpasync16(uint32_t dst, const void* src) {
    asm volatile("cp.async.cg.shared.global [%0], [%1], 16;" :: "r"(dst), "l"(src));
}
#define CPCOMMIT() asm volatile("cp.async.commit_group;" ::: "memory")
#define CPWAIT0()  asm volatile("cp.async.wait_group 0;" ::: "memory")

// ---------------- graph preprocessing ----------------
__global__ void k_zero_deg() {
    int i = blockIdx.x * blockDim.x + threadIdx.x;
    if (i < NN) g_deg[i] = 0;
}
__global__ void k_count(const int* __restrict__ ei) {
    int e = blockIdx.x * blockDim.x + threadIdx.x;
    if (e < EE) atomicAdd(&g_deg[ei[EE + e]], 1);
}
__global__ void k_scan() {
    __shared__ int wsum[32];
    __shared__ int scarry;
    int t = threadIdx.x, lane = t & 31, wid = t >> 5;
    if (t == 0) scarry = 0;
    __syncthreads();
    for (int base = 0; base < NN; base += 1024) {
        int i = base + t;
        int v = (i < NN) ? g_deg[i] : 0;
        int x = v;
        #pragma unroll
        for (int d = 1; d < 32; d <<= 1) {
            int y = __shfl_up_sync(0xffffffffu, x, d);
            if (lane >= d) x += y;
        }
        if (lane == 31) wsum[wid] = x;
        __syncthreads();
        if (wid == 0) {
            int ws = wsum[lane];
            #pragma unroll
            for (int d = 1; d < 32; d <<= 1) {
                int y = __shfl_up_sync(0xffffffffu, ws, d);
                if (lane >= d) ws += y;
            }
            wsum[lane] = ws;
        }
        __syncthreads();
        int carry = scarry;
        int excl = carry + (wid ? wsum[wid - 1] : 0) + (x - v);
        if (i < NN) { g_rowp[i] = excl; g_cur[i] = excl; }
        __syncthreads();
        if (t == 0) scarry = carry + wsum[31];
        __syncthreads();
    }
    if (t == 0) g_rowp[NN] = scarry;
}
__global__ void k_dinv() {
    int i = blockIdx.x * blockDim.x + threadIdx.x;
    if (i < NN) g_dinv[i] = rsqrtf((float)(g_deg[i] + 1));
}
__global__ void k_place(const int* __restrict__ ei) {
    int e = blockIdx.x * blockDim.x + threadIdx.x;
    if (e < EE) {
        int d = ei[EE + e];
        int pos = atomicAdd(&g_cur[d], 1);
        g_esrc[pos] = ei[e];
    }
}

// ---------------- weight precompute: bf16 hi/lo, chunk-packed ----------------
template<int DIN, int DOUT, int NPAD, int NPADP>
__global__ void k_prepw(const float* __restrict__ Wb, const float* __restrict__ Ws,
                        __nv_bfloat16* __restrict__ dst) {
    constexpr int NCH = DIN * 5 / 32;
    int idx = blockIdx.x * blockDim.x + threadIdx.x;
    if (idx >= NCH * 2 * 32 * NPADP) return;
    int n = idx % NPADP;
    int k = (idx / NPADP) & 31;
    int h = (idx / (NPADP * 32)) & 1;
    int c = idx / (NPADP * 32 * 2);
    int kg = c * 32 + k;
    float w = 0.f;
    if (n < DOUT) {
        if (kg < DIN) w = Wb[(size_t)n * DIN + kg];
        else          w = Ws[(size_t)n * (DIN * 4) + (kg - DIN)];
    }
    __nv_bfloat16 hi = __float2bfloat16(w);
    __nv_bfloat16 lo = __float2bfloat16(w - __bfloat162float(hi));
    dst[idx] = h ? lo : hi;
}

// ---------------- stats of x (warp per node): mu0/rs0 + partials ----------------
__global__ void k_statx(const float* __restrict__ x) {
    int gw = (blockIdx.x * blockDim.x + threadIdx.x) >> 5;
    int lane = threadIdx.x & 31;
    if (gw >= NN) return;
    float4 v = ((const float4*)(x + (size_t)gw * 128))[lane];
    float s  = v.x + v.y + v.z + v.w;
    float s2 = v.x * v.x + v.y * v.y + v.z * v.z + v.w * v.w;
    #pragma unroll
    for (int d = 16; d; d >>= 1) {
        s  += __shfl_xor_sync(0xffffffffu, s,  d);
        s2 += __shfl_xor_sync(0xffffffffu, s2, d);
    }
    if (lane == 0) {
        float m = s * (1.f / 128.f);
        g_mu[gw] = m;
        g_rs[gw] = rsqrtf(s2 * (1.f / 128.f) - m * m + 1e-5f);
        g_sA[gw]  = s;
        g_sA2[gw] = s2;
    }
}

// ---------------- fused FastKAN layer via wmma bf16 (3-term compensation) ----------------
template<int DIN>
__device__ __forceinline__ float4 ldx4(const float* __restrict__ a,
                                       const float* __restrict__ b,
                                       const float* __restrict__ c,
                                       int n, int col) {
    if (DIN == 128) return *(const float4*)(a + (size_t)n * 128 + col);
    const float* p = (col < 128) ? a : (col < 256) ? b : c;
    return *(const float4*)(p + (size_t)n * 128 + (col & 127));
}

__device__ __forceinline__ void splitstore(__nv_bfloat16* hiP, __nv_bfloat16* loP,
                                           float4 v) {
    __nv_bfloat162 h0 = __floats2bfloat162_rn(v.x, v.y);
    __nv_bfloat162 h1 = __floats2bfloat162_rn(v.z, v.w);
    float2 f0 = __bfloat1622float2(h0);
    float2 f1 = __bfloat1622float2(h1);
    __nv_bfloat162 l0 = __floats2bfloat162_rn(v.x - f0.x, v.y - f0.y);
    __nv_bfloat162 l1 = __floats2bfloat162_rn(v.z - f1.x, v.w - f1.y);
    ((__nv_bfloat162*)hiP)[0] = h0;
    ((__nv_bfloat162*)hiP)[1] = h1;
    ((__nv_bfloat162*)loP)[0] = l0;
    ((__nv_bfloat162*)loP)[1] = l1;
}

// Double-buffered stages: [aHi TM*ALD][aLo TM*ALD][B hi+lo 2*32*NPADP] per stage.
// 512 threads, 16 warps; warp grid WM x (16/WM); each warp MT m-tiles x NTW n-tiles.
template<int DIN, int DOUT, int NPAD, int NPADP, int OUTP, int OUT_STRIDE, int WM,
         int TM, int THREADS>
__global__ void __launch_bounds__(THREADS)
k_fkan_wmma(const float* __restrict__ in0, const float* __restrict__ in1,
            const float* __restrict__ in2,
            const float* __restrict__ lng, const float* __restrict__ lnb,
            const __nv_bfloat16* __restrict__ wp,
            float* __restrict__ out)
{
    constexpr int NCH   = DIN * 5 / 32;
    constexpr int NT    = NPAD / 16;
    constexpr int WARPS = THREADS / 32;
    constexpr int WN    = WARPS / WM;
    constexpr int MT    = (TM / 16) / WM;
    constexpr int NTW   = NT / WN;
    static_assert(WM * WN == WARPS && MT * WM * 16 == TM && NTW * WN == NT, "tiling");
    constexpr int ALD  = 40;
    constexpr int AELE = TM * ALD;
    constexpr int BELE = 2 * 32 * NPADP;
    constexpr int SELE = 2 * AELE + BELE;

    extern __shared__ char smc[];
    __nv_bfloat16* sb16 = (__nv_bfloat16*)smc;
    const uint32_t sbase = smem_u32(smc);
    float* sOut = (float*)smc;

    const int t = threadIdx.x;
    const int w = t >> 5;
    const int wm = w % WM, wn = w / WM;
    const int base = blockIdx.x * TM;

    const int r = t >> 1, half = t & 1;
    const int n = base + r;
    const bool valid = (n < NN);
    const float mu = valid ? g_mu[n] : 0.f;
    const float rs = valid ? g_rs[n] : 0.f;

    wmma::fragment<wmma::accumulator, 16, 16, 16, float> acc[MT][NTW];
    #pragma unroll
    for (int im = 0; im < MT; im++)
        #pragma unroll
        for (int in = 0; in < NTW; in++) wmma::fill_fragment(acc[im][in], 0.f);

    auto stageA = [&](int c, int s) {
        __nv_bfloat16* aHi = sb16 + s * SELE;
        __nv_bfloat16* aLo = aHi + AELE;
        const int kc = c * 32;
        if (kc < DIN) {
            #pragma unroll
            for (int q = 0; q < 4; q++) {
                const int c0 = half * 16 + q * 4;
                float4 xv = make_float4(0.f, 0.f, 0.f, 0.f);
                if (valid) xv = ldx4<DIN>(in0, in1, in2, n, kc + c0);
                float4 v;
                v.x = __fdividef(xv.x, 1.f + __expf(-xv.x));
                v.y = __fdividef(xv.y, 1.f + __expf(-xv.y));
                v.z = __fdividef(xv.z, 1.f + __expf(-xv.z));
                v.w = __fdividef(xv.w, 1.f + __expf(-xv.w));
                splitstore(aHi + r * ALD + c0, aLo + r * ALD + c0, v);
            }
        } else {
            const int xc = ((kc - DIN) >> 2) + half * 4;
            float4 xv = make_float4(0.f, 0.f, 0.f, 0.f);
            if (valid) xv = ldx4<DIN>(in0, in1, in2, n, xc);
            const float4 gv = *(const float4*)(lng + xc);
            const float4 bv = *(const float4*)(lnb + xc);
            float zz[4];
            zz[0] = (xv.x - mu) * rs * gv.x + bv.x;
            zz[1] = (xv.y - mu) * rs * gv.y + bv.y;
            zz[2] = (xv.z - mu) * rs * gv.z + bv.z;
            zz[3] = (xv.w - mu) * rs * gv.w + bv.w;
            #pragma unroll
            for (int i = 0; i < 4; i++) {
                // rbf chain: rbf0 = exp(-9/16 (z+2)^2); ratio_k = B * e^{2-2k}, B = exp(3z/2)
                const float z = zz[i];
                const float zp2 = z + 2.f;
                const float r0 = __expf(-0.5625f * zp2 * zp2);
                const float B  = __expf(1.5f * z);
                float4 v;
                v.x = r0;
                v.y = r0 * B * 7.3890560989f;   // * e^2
                v.z = v.y * B;                  // * e^0
                v.w = v.z * B * 0.1353352832f;  // * e^-2
                const int c0 = half * 16 + i * 4;
                splitstore(aHi + r * ALD + c0, aLo + r * ALD + c0, v);
            }
        }
    };
    auto stageB = [&](int c, int s) {
        constexpr int NV4 = BELE * 2 / 16;
        const char* src = (const char*)(wp + (size_t)c * BELE);
        const uint32_t dst = sbase + (s * SELE + 2 * AELE) * 2;
        #pragma unroll
        for (int i = t; i < NV4; i += THREADS)
            cpasync16(dst + i * 16, src + i * 16);
    };

    stageB(0, 0);
    CPCOMMIT();
    stageA(0, 0);
    CPWAIT0();
    __syncthreads();

    for (int c = 0; c < NCH; c++) {
        const int s = c & 1;
        if (c + 1 < NCH) { stageB(c + 1, 1 - s); CPCOMMIT(); }

        {
            __nv_bfloat16* aHi = sb16 + s * SELE;
            __nv_bfloat16* aLo = aHi + AELE;
            __nv_bfloat16* bHi = aLo + AELE;
            #pragma unroll
            for (int kk = 0; kk < 2; kk++) {
                wmma::fragment<wmma::matrix_a, 16, 16, 16, __nv_bfloat16, wmma::row_major> ah[MT], al[MT];
                #pragma unroll
                for (int im = 0; im < MT; im++) {
                    const int mrow = (wm * MT + im) * 16;
                    wmma::load_matrix_sync(ah[im], aHi + mrow * ALD + kk * 16, ALD);
                    wmma::load_matrix_sync(al[im], aLo + mrow * ALD + kk * 16, ALD);
                }
                #pragma unroll
                for (int in = 0; in < NTW; in++) {
                    const int col = (wn * NTW + in) * 16;
                    wmma::fragment<wmma::matrix_b, 16, 16, 16, __nv_bfloat16, wmma::row_major> bh, bl;
                    wmma::load_matrix_sync(bh, bHi + kk * 16 * NPADP + col, NPADP);
                    wmma::load_matrix_sync(bl, bHi + 32 * NPADP + kk * 16 * NPADP + col, NPADP);
                    #pragma unroll
                    for (int im = 0; im < MT; im++) {
                        wmma::mma_sync(acc[im][in], ah[im], bh, acc[im][in]);
                        wmma::mma_sync(acc[im][in], ah[im], bl, acc[im][in]);
                        wmma::mma_sync(acc[im][in], al[im], bh, acc[im][in]);
                    }
                }
            }
        }

        if (c + 1 < NCH) stageA(c + 1, 1 - s);
        CPWAIT0();
        __syncthreads();
    }

    // ---- epilogue: accs -> smem -> guarded global store (bias folded into agg) ----
    #pragma unroll
    for (int im = 0; im < MT; im++)
        #pragma unroll
        for (int in = 0; in < NTW; in++)
            wmma::store_matrix_sync(
                sOut + ((wm * MT + im) * 16) * OUTP + (wn * NTW + in) * 16,
                acc[im][in], OUTP, wmma::mem_row_major);
    __syncthreads();

    if (NPAD == 128) {
        for (int e = t; e < TM * 32; e += THREADS) {
            int rr = e >> 5, c4 = e & 31;
            int n2 = base + rr;
            if (n2 < NN)
                ((float4*)(out + (size_t)n2 * OUT_STRIDE))[c4] =
                    *(float4*)&sOut[rr * OUTP + c4 * 4];
        }
    } else {
        for (int e = t; e < TM * NPAD; e += THREADS) {
            int rr = e / NPAD, o = e % NPAD;
            int n2 = base + rr;
            if (o < DOUT && n2 < NN)
                out[(size_t)n2 * OUT_STRIDE + o] = sOut[rr * OUTP + o];
        }
    }
}

// ---------------- aggregation + fused layernorm stats ----------------
__global__ void k_agg128(const float* __restrict__ tin, float* __restrict__ outp,
                         const float* __restrict__ bs, const float* __restrict__ bb,
                         const float* __restrict__ bg, int statmode) {
    int gw = (blockIdx.x * blockDim.x + threadIdx.x) >> 5;
    int lane = threadIdx.x & 31;
    if (gw >= NN) return;
    int beg = g_rowp[gw], end = g_rowp[gw + 1];
    const float4* t4 = (const float4*)tin;
    float4 a = make_float4(0.f, 0.f, 0.f, 0.f);
    float sw = 0.f;
    int j = beg;
    for (; j + 1 < end; j += 2) {
        int s0 = g_esrc[j], s1 = g_esrc[j + 1];
        float w0 = g_dinv[s0], w1 = g_dinv[s1];
        sw += w0 + w1;
        float4 v0 = t4[(size_t)s0 * 32 + lane];
        float4 v1 = t4[(size_t)s1 * 32 + lane];
        a.x += w0 * v0.x + w1 * v1.x;
        a.y += w0 * v0.y + w1 * v1.y;
        a.z += w0 * v0.z + w1 * v1.z;
        a.w += w0 * v0.w + w1 * v1.w;
    }
    if (j < end) {
        int s0 = g_esrc[j];
        float w0 = g_dinv[s0];
        sw += w0;
        float4 v0 = t4[(size_t)s0 * 32 + lane];
        a.x += w0 * v0.x; a.y += w0 * v0.y; a.z += w0 * v0.z; a.w += w0 * v0.w;
    }
    float dn = g_dinv[gw];
    float wb = dn * (sw + dn);
    float4 sv = t4[(size_t)gw * 32 + lane];
    float4 bgv = ((const float4*)bg)[lane];
    float4 bsv = ((const float4*)bs)[lane];
    float4 bbv = ((const float4*)bb)[lane];
    float4 o;
    o.x = dn * (a.x + dn * sv.x) + (bsv.x + bbv.x) * wb + bgv.x;
    o.y = dn * (a.y + dn * sv.y) + (bsv.y + bbv.y) * wb + bgv.y;
    o.z = dn * (a.z + dn * sv.z) + (bsv.z + bbv.z) * wb + bgv.z;
    o.w = dn * (a.w + dn * sv.w) + (bsv.w + bbv.w) * wb + bgv.w;
    ((float4*)outp)[(size_t)gw * 32 + lane] = o;

    float s  = o.x + o.y + o.z + o.w;
    float s2 = o.x * o.x + o.y * o.y + o.z * o.z + o.w * o.w;
    #pragma unroll
    for (int d = 16; d; d >>= 1) {
        s  += __shfl_xor_sync(0xffffffffu, s,  d);
        s2 += __shfl_xor_sync(0xffffffffu, s2, d);
    }
    if (lane == 0) {
        if (statmode == 1) {
            float m = s * (1.f / 128.f);
            g_mu[gw] = m;
            g_rs[gw] = rsqrtf(s2 * (1.f / 128.f) - m * m + 1e-5f);
            g_sA[gw]  += s;
            g_sA2[gw] += s2;
        } else {
            float ts  = g_sA[gw]  + s;
            float ts2 = g_sA2[gw] + s2;
            float m = ts * (1.f / 384.f);
            g_mu[gw] = m;
            g_rs[gw] = rsqrtf(ts2 * (1.f / 384.f) - m * m + 1e-5f);
        }
    }
}

__global__ void k_agg47(const float* __restrict__ tin, float* __restrict__ outp,
                        const float* __restrict__ bs, const float* __restrict__ bb,
                        const float* __restrict__ bg) {
    int gw = (blockIdx.x * blockDim.x + threadIdx.x) >> 5;
    int lane = threadIdx.x & 31;
    if (gw >= NN) return;
    int beg = g_rowp[gw], end = g_rowp[gw + 1];
    float a0 = 0.f, a1 = 0.f, sw = 0.f;
    for (int j = beg; j < end; j++) {
        int s = g_esrc[j];
        float w = g_dinv[s];
        sw += w;
        const float* ts = tin + (size_t)s * 64;
        a0 += w * ts[lane];
        if (lane < 15) a1 += w * ts[32 + lane];
    }
    float dn = g_dinv[gw];
    float wb = dn * (sw + dn);
    const float* tn = tin + (size_t)gw * 64;
    outp[(size_t)gw * 47 + lane] =
        dn * (a0 + dn * tn[lane]) + (bs[lane] + bb[lane]) * wb + bg[lane];
    if (lane < 15)
        outp[(size_t)gw * 47 + 32 + lane] =
            dn * (a1 + dn * tn[32 + lane]) + (bs[32 + lane] + bb[32 + lane]) * wb + bg[32 + lane];
}

// ---------------- driver ----------------
extern "C" void kernel_launch(void* const* d_in, const int* in_sizes, int n_in,
                              void* d_out, int out_size) {
    const float* x    = (const float*)d_in[0];
    const int*   ei   = (const int*)d_in[1];
    const float* lng0 = (const float*)d_in[2];
    const float* lnb0 = (const float*)d_in[3];
    const float* Ws0  = (const float*)d_in[4];
    const float* bs0  = (const float*)d_in[5];
    const float* Wb0  = (const float*)d_in[6];
    const float* bb0  = (const float*)d_in[7];
    const float* bg0  = (const float*)d_in[8];
    const float* lng1 = (const float*)d_in[9];
    const float* lnb1 = (const float*)d_in[10];
    const float* Ws1  = (const float*)d_in[11];
    const float* bs1  = (const float*)d_in[12];
    const float* Wb1  = (const float*)d_in[13];
    const float* bb1  = (const float*)d_in[14];
    const float* bg1  = (const float*)d_in[15];
    const float* lng2 = (const float*)d_in[16];
    const float* lnb2 = (const float*)d_in[17];
    const float* Ws2  = (const float*)d_in[18];
    const float* bs2  = (const float*)d_in[19];
    const float* Wb2  = (const float*)d_in[20];
    const float* bb2  = (const float*)d_in[21];
    const float* bg2  = (const float*)d_in[22];
    float* outp = (float*)d_out;

    void *pt, *ph1, *ph2, *pt2, *pw0, *pw1, *pw2;
    cudaGetSymbolAddress(&pt,  g_t);
    cudaGetSymbolAddress(&ph1, g_h1);
    cudaGetSymbolAddress(&ph2, g_h2);
    cudaGetSymbolAddress(&pt2, g_t2);
    cudaGetSymbolAddress(&pw0, g_wb0);
    cudaGetSymbolAddress(&pw1, g_wb1);
    cudaGetSymbolAddress(&pw2, g_wb2);

    // smem: staging = 2*(2*256*40 + 2*32*NPADP)*2B ; epilogue = 256*OUTP*4B
    const int STG_L01 = 2 * (2 * 256 * 40 + 2 * 32 * 136) * 2;   // 116736
    const int EPI_L01 = 256 * 132 * 4;                            // 135168
    const int SM_L01  = EPI_L01 > STG_L01 ? EPI_L01 : STG_L01;    // 135168
    const int STG_L2  = 2 * (2 * 256 * 40 + 2 * 32 * 56) * 2;    // 96256
    const int EPI_L2  = 256 * 52 * 4;                             // 53248
    const int SM_L2   = STG_L2 > EPI_L2 ? STG_L2 : EPI_L2;        // 96256
    cudaFuncSetAttribute(
        (const void*)k_fkan_wmma<128, 128, 128, 136, 132, 128, 8, 256, 512>,
        cudaFuncAttributeMaxDynamicSharedMemorySize, SM_L01);
    cudaFuncSetAttribute(
        (const void*)k_fkan_wmma<384, 47, 48, 56, 52, 64, 16, 256, 512>,
        cudaFuncAttributeMaxDynamicSharedMemorySize, SM_L2);

    const int FG = (NN + 255) / 256;          // 391
    const int SG = (NN * 32 + 255) / 256;     // warp per node

    // launches 1-5
    k_statx<<<SG, 256>>>(x);
    k_prepw<128, 128, 128, 136><<<(20 * 2 * 32 * 136 + 255) / 256, 256>>>(
        Wb0, Ws0, (__nv_bfloat16*)pw0);
    k_prepw<128, 128, 128, 136><<<(20 * 2 * 32 * 136 + 255) / 256, 256>>>(
        Wb1, Ws1, (__nv_bfloat16*)pw1);
    k_prepw<384, 47, 48, 56><<<(60 * 2 * 32 * 56 + 255) / 256, 256>>>(
        Wb2, Ws2, (__nv_bfloat16*)pw2);
    k_zero_deg<<<(NN + 255) / 256, 256>>>();

    // launch #6: layer-0 fkan
    k_fkan_wmma<128, 128, 128, 136, 132, 128, 8, 256, 512><<<FG, 512, SM_L01>>>(
        x, nullptr, nullptr, lng0, lnb0, (const __nv_bfloat16*)pw0, (float*)pt);

    // graph preprocessing -> CSR + dinv
    k_count<<<(EE + 255) / 256, 256>>>(ei);
    k_scan<<<1, 1024>>>();
    k_dinv<<<(NN + 255) / 256, 256>>>();
    k_place<<<(EE + 255) / 256, 256>>>(ei);

    k_agg128<<<SG, 256>>>((const float*)pt, (float*)ph1, bs0, bb0, bg0, 1);

    // layer 1
    k_fkan_wmma<128, 128, 128, 136, 132, 128, 8, 256, 512><<<FG, 512, SM_L01>>>(
        (const float*)ph1, nullptr, nullptr, lng1, lnb1, (const __nv_bfloat16*)pw1,
        (float*)pt);
    k_agg128<<<SG, 256>>>((const float*)pt, (float*)ph2, bs1, bb1, bg1, 2);

    // layer 2
    k_fkan_wmma<384, 47, 48, 56, 52, 64, 16, 256, 512><<<FG, 512, SM_L2>>>(
        x, (const float*)ph1, (const float*)ph2, lng2, lnb2,
        (const __nv_bfloat16*)pw2, (float*)pt2);
    k_agg47<<<SG, 256>>>((const float*)pt2, outp, bs2, bb2, bg2);
}